// round 7
// baseline (speedup 1.0000x reference)
#include <cuda_runtime.h>
#include <cstdint>

// BiAttention (BiDAF): N=64, T=1024, J=64, D2=200.
// G = concat([H, U_, H*U_, H*H_], -1) -> (64, 1024, 800) fp32.

#define NEGV (-10000000.0f)

__device__ float g_Smax[64 * 1024];

typedef unsigned long long ull;

// ---- shared layout (floats) ----
#define SU   204
#define SXH  108
#define SPS  68
#define SUC_STRIDE 516
#define OFF_U    0
#define OFF_X    13056
#define OFF_HWH  26880
#define OFF_UWU  27008
#define OFF_QM   27072
#define OFF_W    27136
#define SMEM_FLOATS 27736
#define SMEM_BYTES  (SMEM_FLOATS * 4)   // 110944 -> 2 CTAs/SM

__device__ __forceinline__ void fma2(ull& acc, ull a, ull b) {
    asm("fma.rn.f32x2 %0, %1, %2, %0;" : "+l"(acc) : "l"(a), "l"(b));
}
__device__ __forceinline__ ull dup2(float x) {
    ull r; unsigned xi = __float_as_uint(x);
    asm("mov.b64 %0, {%1, %1};" : "=l"(r) : "r"(xi));
    return r;
}
__device__ __forceinline__ float lo32(ull v) { return __uint_as_float((unsigned)v); }
__device__ __forceinline__ float hi32(ull v) { return __uint_as_float((unsigned)(v >> 32)); }

union F4U2 { float4 f; ull u[2]; };

__device__ __forceinline__ unsigned smem_u32(const void* p) {
    unsigned a;
    asm("{ .reg .u64 t; cvta.to.shared.u64 t, %1; cvt.u32.u64 %0, t; }" : "=r"(a) : "l"(p));
    return a;
}
__device__ __forceinline__ void st_cluster_f32(unsigned laddr, int rank, float v) {
    asm volatile("{ .reg .b32 ra; mapa.shared::cluster.u32 ra, %0, %1; st.shared::cluster.f32 [ra], %2; }"
                 :: "r"(laddr), "r"(rank), "f"(v) : "memory");
}
__device__ __forceinline__ float ld_cluster_f32(unsigned laddr, int rank) {
    float v;
    asm volatile("{ .reg .b32 ra; mapa.shared::cluster.u32 ra, %1, %2; ld.shared::cluster.f32 %0, [ra]; }"
                 : "=f"(v) : "r"(laddr), "r"(rank) : "memory");
    return v;
}
#define CLUSTER_SYNC_() do { \
    asm volatile("barrier.cluster.arrive.aligned;" ::: "memory"); \
    asm volatile("barrier.cluster.wait.aligned;" ::: "memory"); } while (0)

__global__ void __launch_bounds__(256, 2)
bi_attn_main(const float* __restrict__ H, const float* __restrict__ U,
             const float* __restrict__ q_mask, const float* __restrict__ wv,
             const float* __restrict__ bptr, float* __restrict__ G)
{
    extern __shared__ float sm[];
    float* sU   = sm + OFF_U;
    float* sPs  = sm + OFF_U;    // ALIAS after repack
    float* sH   = sm + OFF_X;
    float* sUc  = sm + OFF_X;    // ALIAS after GEMM
    float* sHwh = sm + OFF_HWH;
    float* sUwu = sm + OFF_UWU;
    float* sQm  = sm + OFF_QM;
    float* sW   = sm + OFF_W;

    const int tid = threadIdx.x;
    const int n   = blockIdx.y;
    const int m0  = blockIdx.x * 128;

    for (int i = tid; i < 600; i += 256) sW[i] = wv[i];
    if (tid < 64) sQm[tid] = q_mask[n * 64 + tid];
    __syncthreads();

    const float bval = bptr[0];

    // ---- stage U full + uwu ----
    {
        const int j  = tid >> 2;
        const int kg = tid & 3;
        const float* urow = U + (size_t)(n * 64 + j) * 200;
        float uwu = 0.f;
        #pragma unroll
        for (int c = kg; c < 50; c += 4) {
            float4 u4  = *(const float4*)(urow + c * 4);
            float4 wu4 = *(const float4*)(sW + 200 + c * 4);
            uwu += u4.x * wu4.x + u4.y * wu4.y + u4.z * wu4.z + u4.w * wu4.w;
            *(float4*)(sU + j * SU + c * 4) = u4;
        }
        uwu += __shfl_xor_sync(0xffffffffu, uwu, 1);
        uwu += __shfl_xor_sync(0xffffffffu, uwu, 2);
        if (kg == 0) sUwu[j] = uwu;
    }

    const int hrowi = tid >> 1;
    const int hkg   = tid & 1;
    const float* hrow = H + (size_t)(n * 1024 + m0 + hrowi) * 200;
    float hwh_acc = 0.f;

    #pragma unroll
    for (int c = hkg; c < 25; c += 2) {
        const int k = c * 4;
        float4 h4   = *(const float4*)(hrow + k);
        float4 wh4  = *(const float4*)(sW + k);
        float4 whu4 = *(const float4*)(sW + 400 + k);
        hwh_acc += h4.x * wh4.x + h4.y * wh4.y + h4.z * wh4.z + h4.w * wh4.w;
        float4 hs;
        hs.x = h4.x * whu4.x; hs.y = h4.y * whu4.y;
        hs.z = h4.z * whu4.z; hs.w = h4.w * whu4.w;
        *(float4*)(sH + hrowi * SXH + k) = hs;
    }
    __syncthreads();

    const int mg = tid >> 3;
    const int tj = tid & 7;

    ull acc[4][8];
    #pragma unroll
    for (int i = 0; i < 4; i++)
        #pragma unroll
        for (int jj = 0; jj < 8; jj++) acc[i][jj] = 0ull;

    const float* aBase = sH + mg * 4 * SXH;
    const float* bBase = sU + tj * SU;

    // ---- GEMM half 0 : all 12 loads up front per iter ----
    #pragma unroll 1
    for (int kc = 0; kc < 25; kc++) {
        const int k = kc * 4;
        F4U2 a0, a1, a2, a3, b[8];
        a0.f = *(const float4*)(aBase + k);
        a1.f = *(const float4*)(aBase + SXH + k);
        a2.f = *(const float4*)(aBase + 2 * SXH + k);
        a3.f = *(const float4*)(aBase + 3 * SXH + k);
        #pragma unroll
        for (int jj = 0; jj < 8; jj++)
            b[jj].f = *(const float4*)(bBase + jj * (8 * SU) + k);
        #pragma unroll
        for (int jj = 0; jj < 8; jj++) {
            fma2(acc[0][jj], a0.u[0], b[jj].u[0]); fma2(acc[0][jj], a0.u[1], b[jj].u[1]);
            fma2(acc[1][jj], a1.u[0], b[jj].u[0]); fma2(acc[1][jj], a1.u[1], b[jj].u[1]);
            fma2(acc[2][jj], a2.u[0], b[jj].u[0]); fma2(acc[2][jj], a2.u[1], b[jj].u[1]);
            fma2(acc[3][jj], a3.u[0], b[jj].u[0]); fma2(acc[3][jj], a3.u[1], b[jj].u[1]);
        }
    }
    __syncthreads();

    // stage H half 1, finalize hwh
    #pragma unroll
    for (int c = hkg; c < 25; c += 2) {
        const int k = 100 + c * 4;
        float4 h4   = *(const float4*)(hrow + k);
        float4 wh4  = *(const float4*)(sW + k);
        float4 whu4 = *(const float4*)(sW + 400 + k);
        hwh_acc += h4.x * wh4.x + h4.y * wh4.y + h4.z * wh4.z + h4.w * wh4.w;
        float4 hs;
        hs.x = h4.x * whu4.x; hs.y = h4.y * whu4.y;
        hs.z = h4.z * whu4.z; hs.w = h4.w * whu4.w;
        *(float4*)(sH + hrowi * SXH + c * 4) = hs;
    }
    {
        float hv = hwh_acc + __shfl_xor_sync(0xffffffffu, hwh_acc, 1);
        if (hkg == 0) sHwh[hrowi] = hv;
    }
    __syncthreads();

    // ---- GEMM half 1 ----
    #pragma unroll 1
    for (int kc = 0; kc < 25; kc++) {
        const int k = kc * 4;
        F4U2 a0, a1, a2, a3, b[8];
        a0.f = *(const float4*)(aBase + k);
        a1.f = *(const float4*)(aBase + SXH + k);
        a2.f = *(const float4*)(aBase + 2 * SXH + k);
        a3.f = *(const float4*)(aBase + 3 * SXH + k);
        #pragma unroll
        for (int jj = 0; jj < 8; jj++)
            b[jj].f = *(const float4*)(bBase + 100 + jj * (8 * SU) + k);
        #pragma unroll
        for (int jj = 0; jj < 8; jj++) {
            fma2(acc[0][jj], a0.u[0], b[jj].u[0]); fma2(acc[0][jj], a0.u[1], b[jj].u[1]);
            fma2(acc[1][jj], a1.u[0], b[jj].u[0]); fma2(acc[1][jj], a1.u[1], b[jj].u[1]);
            fma2(acc[2][jj], a2.u[0], b[jj].u[0]); fma2(acc[2][jj], a2.u[1], b[jj].u[1]);
            fma2(acc[3][jj], a3.u[0], b[jj].u[0]); fma2(acc[3][jj], a3.u[1], b[jj].u[1]);
        }
    }
    __syncthreads();

    // ---- repack U chunk-major ----
    #pragma unroll 1
    for (int idx = tid; idx < 1600; idx += 256) {
        const int chunk = idx >> 6;
        const int j     = idx & 63;
        const float4 vA = *(const float4*)(sU + j * SU + chunk * 8);
        const float4 vB = *(const float4*)(sU + j * SU + chunk * 8 + 4);
        *(float4*)(sUc + chunk * SUC_STRIDE + j * 8)     = vA;
        *(float4*)(sUc + chunk * SUC_STRIDE + j * 8 + 4) = vB;
    }

    // ---- softmax over j for 4 rows ----
    float pv[4][8];
    #pragma unroll 1
    for (int i = 0; i < 4; i++) {
        const int m = mg * 4 + i;
        const float hwh = sHwh[m];
        float vmv[8], qv[8];
        float mx = -3.4e38f, smx = -3.4e38f;
        #pragma unroll
        for (int jj = 0; jj < 8; jj++) {
            const int j = tj + 8 * jj;
            const ull v = acc[i][jj];
            const float s = lo32(v) + hi32(v) + hwh + sUwu[j] + bval;
            const float q = sQm[j];
            const float vm = s * q;
            vmv[jj] = vm; qv[jj] = q;
            mx  = fmaxf(mx, vm);
            smx = fmaxf(smx, (q != 0.f) ? s : NEGV);
        }
        mx  = fmaxf(mx,  __shfl_xor_sync(0xffffffffu, mx, 1));
        mx  = fmaxf(mx,  __shfl_xor_sync(0xffffffffu, mx, 2));
        mx  = fmaxf(mx,  __shfl_xor_sync(0xffffffffu, mx, 4));
        smx = fmaxf(smx, __shfl_xor_sync(0xffffffffu, smx, 1));
        smx = fmaxf(smx, __shfl_xor_sync(0xffffffffu, smx, 2));
        smx = fmaxf(smx, __shfl_xor_sync(0xffffffffu, smx, 4));
        float E = 0.f, M = 0.f, ev[8];
        #pragma unroll
        for (int jj = 0; jj < 8; jj++) {
            const float e = __expf(vmv[jj] - mx);
            ev[jj] = e; E += e; M += e * qv[jj];
        }
        E += __shfl_xor_sync(0xffffffffu, E, 1);
        E += __shfl_xor_sync(0xffffffffu, E, 2);
        E += __shfl_xor_sync(0xffffffffu, E, 4);
        M += __shfl_xor_sync(0xffffffffu, M, 1);
        M += __shfl_xor_sync(0xffffffffu, M, 2);
        M += __shfl_xor_sync(0xffffffffu, M, 4);
        const float inv = 1.0f / (M + 1e-13f * E);
        #pragma unroll
        for (int jj = 0; jj < 8; jj++) pv[i][jj] = ev[jj] * qv[jj] * inv;
        if (tj == 0) g_Smax[(n << 10) + m0 + m] = smx;
    }
    __syncthreads();

    #pragma unroll
    for (int i = 0; i < 4; i++) {
        const int m = mg * 4 + i;
        #pragma unroll
        for (int jj = 0; jj < 8; jj++)
            sPs[m * SPS + tj + 8 * jj] = pv[i][jj];
    }
    __syncthreads();

    // ---- Phase C: U_ = P @ U ----
    const int rg = tid >> 4;
    const int dl = tid & 15;
    const float* pRow = sPs + rg * 8 * SPS;
    const float* HrowC = H + (size_t)(n * 1024 + m0 + rg * 8) * 200;
    float*       GrowC = G + (size_t)(n * 1024 + m0 + rg * 8) * 800;

    #pragma unroll 1
    for (int p = 0; p < 2; p++) {
        const int chunk = p * 16 + dl;
        const bool valid = (chunk < 25);
        const int cs = valid ? chunk : 0;
        const int d0 = cs * 8;
        const float* uc = sUc + cs * SUC_STRIDE;

        ull acc2[8][4];
        #pragma unroll
        for (int r = 0; r < 8; r++)
            #pragma unroll
            for (int u = 0; u < 4; u++) acc2[r][u] = 0ull;

        #pragma unroll 1
        for (int j = 0; j < 64; j += 4) {
            float4 P[8];
            #pragma unroll
            for (int r = 0; r < 8; r++)
                P[r] = *(const float4*)(pRow + r * SPS + j);
            #pragma unroll
            for (int q = 0; q < 4; q++) {
                const float* up = uc + (j + q) * 8;
                F4U2 bA, bB;
                bA.f = *(const float4*)(up);
                bB.f = *(const float4*)(up + 4);
                const float* Pq = (const float*)P;
                #pragma unroll
                for (int r = 0; r < 8; r++) {
                    const ull d = dup2(Pq[r * 4 + q]);
                    fma2(acc2[r][0], d, bA.u[0]);
                    fma2(acc2[r][1], d, bA.u[1]);
                    fma2(acc2[r][2], d, bB.u[0]);
                    fma2(acc2[r][3], d, bB.u[1]);
                }
            }
        }

        if (valid) {
            #pragma unroll
            for (int r = 0; r < 8; r++) {
                float4 uA, uB;
                uA.x = lo32(acc2[r][0]); uA.y = hi32(acc2[r][0]);
                uA.z = lo32(acc2[r][1]); uA.w = hi32(acc2[r][1]);
                uB.x = lo32(acc2[r][2]); uB.y = hi32(acc2[r][2]);
                uB.z = lo32(acc2[r][3]); uB.w = hi32(acc2[r][3]);
                const float4 hA = *(const float4*)(HrowC + r * 200 + d0);
                const float4 hB = *(const float4*)(HrowC + r * 200 + d0 + 4);
                float* gp = GrowC + (size_t)r * 800;
                *(float4*)(gp + d0)           = hA;
                *(float4*)(gp + d0 + 4)       = hB;
                *(float4*)(gp + 200 + d0)     = uA;
                *(float4*)(gp + 200 + d0 + 4) = uB;
                float4 mA, mB;
                mA.x = hA.x * uA.x; mA.y = hA.y * uA.y; mA.z = hA.z * uA.z; mA.w = hA.w * uA.w;
                mB.x = hB.x * uB.x; mB.y = hB.y * uB.y; mB.z = hB.z * uB.z; mB.w = hB.w * uB.w;
                *(float4*)(gp + 400 + d0)     = mA;
                *(float4*)(gp + 400 + d0 + 4) = mB;
            }
        }
    }
}

// ---- fused tail: cluster of 8 CTAs per n; softmax(Smax) + Hbar + H*Hbar ----
__global__ void __launch_bounds__(256, 1) __cluster_dims__(8, 1, 1)
tail_fused(const float* __restrict__ H, const float* __restrict__ c_mask,
           float* __restrict__ G)
{
    __shared__ float sa[128];
    __shared__ float s_mx[8], s_E[8], s_M[8];
    __shared__ float red[8], redE[8], redM[8];
    __shared__ float part[8][208];
    __shared__ float ppart[200];
    __shared__ float hbar[200];

    const int bx = blockIdx.x;
    const int n = bx >> 3;
    const int s = bx & 7;           // == cluster rank
    const int tid = threadIdx.x;
    const int wid = tid >> 5, lane = tid & 31;

    // local chunk v, c
    float v = -3.4e38f, c = 0.f;
    if (tid < 128) {
        c = c_mask[n * 1024 + s * 128 + tid];
        v = g_Smax[n * 1024 + s * 128 + tid] * c;
    }
    // block max
    float mx = v;
    #pragma unroll
    for (int o = 16; o > 0; o >>= 1) mx = fmaxf(mx, __shfl_xor_sync(0xffffffffu, mx, o));
    if (lane == 0) red[wid] = mx;
    __syncthreads();
    mx = red[0];
    #pragma unroll
    for (int i = 1; i < 8; i++) mx = fmaxf(mx, red[i]);

    // broadcast local max to all ranks' s_mx[s]
    if (tid == 0) {
        const unsigned a = smem_u32(&s_mx[s]);
        #pragma unroll
        for (int r = 0; r < 8; r++) st_cluster_f32(a, r, mx);
    }
    CLUSTER_SYNC_();

    float gmx = s_mx[0];
    #pragma unroll
    for (int i = 1; i < 8; i++) gmx = fmaxf(gmx, s_mx[i]);

    // local E, M ; stash unscaled e*c in sa
    float e = 0.f;
    if (tid < 128) {
        e = __expf(v - gmx);
        sa[tid] = e * c;
    }
    float El = e, Ml = e * c;
    #pragma unroll
    for (int o = 16; o > 0; o >>= 1) {
        El += __shfl_xor_sync(0xffffffffu, El, o);
        Ml += __shfl_xor_sync(0xffffffffu, Ml, o);
    }
    if (lane == 0) { redE[wid] = El; redM[wid] = Ml; }
    __syncthreads();
    El = 0.f; Ml = 0.f;
    #pragma unroll
    for (int i = 0; i < 8; i++) { El += redE[i]; Ml += redM[i]; }
    if (tid == 0) {
        const unsigned aE = smem_u32(&s_E[s]);
        const unsigned aM = smem_u32(&s_M[s]);
        #pragma unroll
        for (int r = 0; r < 8; r++) { st_cluster_f32(aE, r, El); st_cluster_f32(aM, r, Ml); }
    }
    CLUSTER_SYNC_();

    float Et = 0.f, Mt = 0.f;
    #pragma unroll
    for (int i = 0; i < 8; i++) { Et += s_E[i]; Mt += s_M[i]; }
    const float inv = 1.0f / (Mt + 1e-13f * Et);

    // partial Hbar over this chunk's 128 rows (unscaled weights sa)
    const int d0v = lane * 4;
    const int d1v = 128 + lane * 4;
    const bool v1 = (lane < 18);
    float4 a0 = {0.f, 0.f, 0.f, 0.f}, a1 = {0.f, 0.f, 0.f, 0.f};
    const float* hb = H + (size_t)n * 204800 + (size_t)s * 128 * 200;
    #pragma unroll 4
    for (int t = wid * 16; t < wid * 16 + 16; t++) {
        const float av = sa[t];
        const float* hr = hb + (size_t)t * 200;
        const float4 h0 = *(const float4*)(hr + d0v);
        a0.x += av * h0.x; a0.y += av * h0.y; a0.z += av * h0.z; a0.w += av * h0.w;
        if (v1) {
            const float4 h1 = *(const float4*)(hr + d1v);
            a1.x += av * h1.x; a1.y += av * h1.y; a1.z += av * h1.z; a1.w += av * h1.w;
        }
    }
    *(float4*)(&part[wid][d0v]) = a0;
    if (v1) *(float4*)(&part[wid][d1v]) = a1;
    __syncthreads();

    if (tid < 200) {
        float sum = 0.f;
        #pragma unroll
        for (int w = 0; w < 8; w++) sum += part[w][tid];
        ppart[tid] = sum;
    }
    CLUSTER_SYNC_();   // all ranks' ppart ready

    if (tid < 200) {
        const unsigned a = smem_u32(&ppart[tid]);
        float sum = 0.f;
        #pragma unroll
        for (int r = 0; r < 8; r++) sum += ld_cluster_f32(a, r);
        hbar[tid] = sum * inv;
    }
    CLUSTER_SYNC_();   // all ranks done reading peers' ppart
    __syncthreads();

    // product: G[n, chunk rows, 600:800] = H * hbar
    float* gb = G + (size_t)(n * 1024 + s * 128) * 800;
    #pragma unroll 1
    for (int i = tid; i < 6400; i += 256) {
        const int r = i / 50;
        const int cc = i - r * 50;
        const float4 h4 = *(const float4*)(hb + (size_t)r * 200 + cc * 4);
        const float4 b4 = *(const float4*)(hbar + cc * 4);
        float4 o;
        o.x = h4.x * b4.x; o.y = h4.y * b4.y; o.z = h4.z * b4.z; o.w = h4.w * b4.w;
        *(float4*)(gb + (size_t)r * 800 + 600 + cc * 4) = o;
    }
}

extern "C" void kernel_launch(void* const* d_in, const int* in_sizes, int n_in,
                              void* d_out, int out_size)
{
    const float* H      = (const float*)d_in[0];
    const float* U      = (const float*)d_in[1];
    const float* c_mask = (const float*)d_in[2];
    const float* q_mask = (const float*)d_in[3];
    const float* w      = (const float*)d_in[4];
    const float* b      = (const float*)d_in[5];
    float* G = (float*)d_out;

    cudaFuncSetAttribute(bi_attn_main, cudaFuncAttributeMaxDynamicSharedMemorySize, SMEM_BYTES);

    dim3 g1(8, 64);
    bi_attn_main<<<g1, 256, SMEM_BYTES>>>(H, U, q_mask, w, b, G);
    tail_fused<<<512, 256>>>(H, c_mask, G);
}

// round 8
// speedup vs baseline: 1.0030x; 1.0030x over previous
#include <cuda_runtime.h>
#include <cstdint>

// BiAttention (BiDAF): N=64, T=1024, J=64, D2=200.
// G = concat([H, U_, H*U_, H*H_], -1) -> (64, 1024, 800) fp32.

#define NEGV (-10000000.0f)

__device__ float g_Smax[64 * 1024];

typedef unsigned long long ull;

// ---- shared layout (floats) ----
#define SU   204
#define SXH  108
#define SPS  68
#define SUC_STRIDE 516
#define OFF_U    0
#define OFF_X    13056
#define OFF_HWH  26880
#define OFF_UWU  27008
#define OFF_QM   27072
#define OFF_W    27136
#define SMEM_FLOATS 27736
#define SMEM_BYTES  (SMEM_FLOATS * 4)   // 110944 -> 2 CTAs/SM

__device__ __forceinline__ void fma2(ull& acc, ull a, ull b) {
    asm("fma.rn.f32x2 %0, %1, %2, %0;" : "+l"(acc) : "l"(a), "l"(b));
}
__device__ __forceinline__ ull dup2(float x) {
    ull r; unsigned xi = __float_as_uint(x);
    asm("mov.b64 %0, {%1, %1};" : "=l"(r) : "r"(xi));
    return r;
}
__device__ __forceinline__ float lo32(ull v) { return __uint_as_float((unsigned)v); }
__device__ __forceinline__ float hi32(ull v) { return __uint_as_float((unsigned)(v >> 32)); }

union F4U2 { float4 f; ull u[2]; };

__device__ __forceinline__ unsigned smem_u32(const void* p) {
    unsigned a;
    asm("{ .reg .u64 t; cvta.to.shared.u64 t, %1; cvt.u32.u64 %0, t; }" : "=r"(a) : "l"(p));
    return a;
}
__device__ __forceinline__ void st_cluster_f32(unsigned laddr, int rank, float v) {
    asm volatile("{ .reg .b32 ra; mapa.shared::cluster.u32 ra, %0, %1; st.shared::cluster.f32 [ra], %2; }"
                 :: "r"(laddr), "r"(rank), "f"(v) : "memory");
}
__device__ __forceinline__ float ld_cluster_f32(unsigned laddr, int rank) {
    float v;
    asm volatile("{ .reg .b32 ra; mapa.shared::cluster.u32 ra, %1, %2; ld.shared::cluster.f32 %0, [ra]; }"
                 : "=f"(v) : "r"(laddr), "r"(rank) : "memory");
    return v;
}
#define CLUSTER_SYNC_() do { \
    asm volatile("barrier.cluster.arrive.aligned;" ::: "memory"); \
    asm volatile("barrier.cluster.wait.aligned;" ::: "memory"); } while (0)

__global__ void __launch_bounds__(256, 2)
bi_attn_main(const float* __restrict__ H, const float* __restrict__ U,
             const float* __restrict__ q_mask, const float* __restrict__ wv,
             const float* __restrict__ bptr, float* __restrict__ G)
{
    extern __shared__ float sm[];
    float* sU   = sm + OFF_U;
    float* sPs  = sm + OFF_U;    // ALIAS after repack
    float* sH   = sm + OFF_X;
    float* sUc  = sm + OFF_X;    // ALIAS after GEMM
    float* sHwh = sm + OFF_HWH;
    float* sUwu = sm + OFF_UWU;
    float* sQm  = sm + OFF_QM;
    float* sW   = sm + OFF_W;

    const int tid = threadIdx.x;
    const int n   = blockIdx.y;
    const int m0  = blockIdx.x * 128;

    for (int i = tid; i < 600; i += 256) sW[i] = wv[i];
    if (tid < 64) sQm[tid] = q_mask[n * 64 + tid];
    __syncthreads();

    const float bval = bptr[0];

    // ---- stage U full + uwu ----
    {
        const int j  = tid >> 2;
        const int kg = tid & 3;
        const float* urow = U + (size_t)(n * 64 + j) * 200;
        float uwu = 0.f;
        #pragma unroll
        for (int c = kg; c < 50; c += 4) {
            float4 u4  = *(const float4*)(urow + c * 4);
            float4 wu4 = *(const float4*)(sW + 200 + c * 4);
            uwu += u4.x * wu4.x + u4.y * wu4.y + u4.z * wu4.z + u4.w * wu4.w;
            *(float4*)(sU + j * SU + c * 4) = u4;
        }
        uwu += __shfl_xor_sync(0xffffffffu, uwu, 1);
        uwu += __shfl_xor_sync(0xffffffffu, uwu, 2);
        if (kg == 0) sUwu[j] = uwu;
    }

    const int hrowi = tid >> 1;
    const int hkg   = tid & 1;
    const float* hrow = H + (size_t)(n * 1024 + m0 + hrowi) * 200;
    float hwh_acc = 0.f;

    #pragma unroll
    for (int c = hkg; c < 25; c += 2) {
        const int k = c * 4;
        float4 h4   = *(const float4*)(hrow + k);
        float4 wh4  = *(const float4*)(sW + k);
        float4 whu4 = *(const float4*)(sW + 400 + k);
        hwh_acc += h4.x * wh4.x + h4.y * wh4.y + h4.z * wh4.z + h4.w * wh4.w;
        float4 hs;
        hs.x = h4.x * whu4.x; hs.y = h4.y * whu4.y;
        hs.z = h4.z * whu4.z; hs.w = h4.w * whu4.w;
        *(float4*)(sH + hrowi * SXH + k) = hs;
    }
    __syncthreads();

    const int mg = tid >> 3;
    const int tj = tid & 7;

    ull acc[4][8];
    #pragma unroll
    for (int i = 0; i < 4; i++)
        #pragma unroll
        for (int jj = 0; jj < 8; jj++) acc[i][jj] = 0ull;

    const float* aBase = sH + mg * 4 * SXH;
    const float* bBase = sU + tj * SU;

    // ---- GEMM half 0 : all 12 loads up front per iter ----
    #pragma unroll 1
    for (int kc = 0; kc < 25; kc++) {
        const int k = kc * 4;
        F4U2 a0, a1, a2, a3, b[8];
        a0.f = *(const float4*)(aBase + k);
        a1.f = *(const float4*)(aBase + SXH + k);
        a2.f = *(const float4*)(aBase + 2 * SXH + k);
        a3.f = *(const float4*)(aBase + 3 * SXH + k);
        #pragma unroll
        for (int jj = 0; jj < 8; jj++)
            b[jj].f = *(const float4*)(bBase + jj * (8 * SU) + k);
        #pragma unroll
        for (int jj = 0; jj < 8; jj++) {
            fma2(acc[0][jj], a0.u[0], b[jj].u[0]); fma2(acc[0][jj], a0.u[1], b[jj].u[1]);
            fma2(acc[1][jj], a1.u[0], b[jj].u[0]); fma2(acc[1][jj], a1.u[1], b[jj].u[1]);
            fma2(acc[2][jj], a2.u[0], b[jj].u[0]); fma2(acc[2][jj], a2.u[1], b[jj].u[1]);
            fma2(acc[3][jj], a3.u[0], b[jj].u[0]); fma2(acc[3][jj], a3.u[1], b[jj].u[1]);
        }
    }
    __syncthreads();

    // stage H half 1, finalize hwh
    #pragma unroll
    for (int c = hkg; c < 25; c += 2) {
        const int k = 100 + c * 4;
        float4 h4   = *(const float4*)(hrow + k);
        float4 wh4  = *(const float4*)(sW + k);
        float4 whu4 = *(const float4*)(sW + 400 + k);
        hwh_acc += h4.x * wh4.x + h4.y * wh4.y + h4.z * wh4.z + h4.w * wh4.w;
        float4 hs;
        hs.x = h4.x * whu4.x; hs.y = h4.y * whu4.y;
        hs.z = h4.z * whu4.z; hs.w = h4.w * whu4.w;
        *(float4*)(sH + hrowi * SXH + c * 4) = hs;
    }
    {
        float hv = hwh_acc + __shfl_xor_sync(0xffffffffu, hwh_acc, 1);
        if (hkg == 0) sHwh[hrowi] = hv;
    }
    __syncthreads();

    // ---- GEMM half 1 ----
    #pragma unroll 1
    for (int kc = 0; kc < 25; kc++) {
        const int k = kc * 4;
        F4U2 a0, a1, a2, a3, b[8];
        a0.f = *(const float4*)(aBase + k);
        a1.f = *(const float4*)(aBase + SXH + k);
        a2.f = *(const float4*)(aBase + 2 * SXH + k);
        a3.f = *(const float4*)(aBase + 3 * SXH + k);
        #pragma unroll
        for (int jj = 0; jj < 8; jj++)
            b[jj].f = *(const float4*)(bBase + 100 + jj * (8 * SU) + k);
        #pragma unroll
        for (int jj = 0; jj < 8; jj++) {
            fma2(acc[0][jj], a0.u[0], b[jj].u[0]); fma2(acc[0][jj], a0.u[1], b[jj].u[1]);
            fma2(acc[1][jj], a1.u[0], b[jj].u[0]); fma2(acc[1][jj], a1.u[1], b[jj].u[1]);
            fma2(acc[2][jj], a2.u[0], b[jj].u[0]); fma2(acc[2][jj], a2.u[1], b[jj].u[1]);
            fma2(acc[3][jj], a3.u[0], b[jj].u[0]); fma2(acc[3][jj], a3.u[1], b[jj].u[1]);
        }
    }
    __syncthreads();

    // ---- repack U chunk-major ----
    #pragma unroll 1
    for (int idx = tid; idx < 1600; idx += 256) {
        const int chunk = idx >> 6;
        const int j     = idx & 63;
        const float4 vA = *(const float4*)(sU + j * SU + chunk * 8);
        const float4 vB = *(const float4*)(sU + j * SU + chunk * 8 + 4);
        *(float4*)(sUc + chunk * SUC_STRIDE + j * 8)     = vA;
        *(float4*)(sUc + chunk * SUC_STRIDE + j * 8 + 4) = vB;
    }

    // ---- softmax over j for 4 rows ----
    float pv[4][8];
    #pragma unroll 1
    for (int i = 0; i < 4; i++) {
        const int m = mg * 4 + i;
        const float hwh = sHwh[m];
        float vmv[8], qv[8];
        float mx = -3.4e38f, smx = -3.4e38f;
        #pragma unroll
        for (int jj = 0; jj < 8; jj++) {
            const int j = tj + 8 * jj;
            const ull v = acc[i][jj];
            const float s = lo32(v) + hi32(v) + hwh + sUwu[j] + bval;
            const float q = sQm[j];
            const float vm = s * q;
            vmv[jj] = vm; qv[jj] = q;
            mx  = fmaxf(mx, vm);
            smx = fmaxf(smx, (q != 0.f) ? s : NEGV);
        }
        mx  = fmaxf(mx,  __shfl_xor_sync(0xffffffffu, mx, 1));
        mx  = fmaxf(mx,  __shfl_xor_sync(0xffffffffu, mx, 2));
        mx  = fmaxf(mx,  __shfl_xor_sync(0xffffffffu, mx, 4));
        smx = fmaxf(smx, __shfl_xor_sync(0xffffffffu, smx, 1));
        smx = fmaxf(smx, __shfl_xor_sync(0xffffffffu, smx, 2));
        smx = fmaxf(smx, __shfl_xor_sync(0xffffffffu, smx, 4));
        float E = 0.f, M = 0.f, ev[8];
        #pragma unroll
        for (int jj = 0; jj < 8; jj++) {
            const float e = __expf(vmv[jj] - mx);
            ev[jj] = e; E += e; M += e * qv[jj];
        }
        E += __shfl_xor_sync(0xffffffffu, E, 1);
        E += __shfl_xor_sync(0xffffffffu, E, 2);
        E += __shfl_xor_sync(0xffffffffu, E, 4);
        M += __shfl_xor_sync(0xffffffffu, M, 1);
        M += __shfl_xor_sync(0xffffffffu, M, 2);
        M += __shfl_xor_sync(0xffffffffu, M, 4);
        const float inv = 1.0f / (M + 1e-13f * E);
        #pragma unroll
        for (int jj = 0; jj < 8; jj++) pv[i][jj] = ev[jj] * qv[jj] * inv;
        if (tj == 0) g_Smax[(n << 10) + m0 + m] = smx;
    }
    __syncthreads();

    #pragma unroll
    for (int i = 0; i < 4; i++) {
        const int m = mg * 4 + i;
        #pragma unroll
        for (int jj = 0; jj < 8; jj++)
            sPs[m * SPS + tj + 8 * jj] = pv[i][jj];
    }
    __syncthreads();

    // ---- Phase C: U_ = P @ U ----
    const int rg = tid >> 4;
    const int dl = tid & 15;
    const float* pRow = sPs + rg * 8 * SPS;
    const float* HrowC = H + (size_t)(n * 1024 + m0 + rg * 8) * 200;
    float*       GrowC = G + (size_t)(n * 1024 + m0 + rg * 8) * 800;

    #pragma unroll 1
    for (int p = 0; p < 2; p++) {
        const int chunk = p * 16 + dl;
        const bool valid = (chunk < 25);
        const int cs = valid ? chunk : 0;
        const int d0 = cs * 8;
        const float* uc = sUc + cs * SUC_STRIDE;

        ull acc2[8][4];
        #pragma unroll
        for (int r = 0; r < 8; r++)
            #pragma unroll
            for (int u = 0; u < 4; u++) acc2[r][u] = 0ull;

        #pragma unroll 1
        for (int j = 0; j < 64; j += 4) {
            float4 P[8];
            #pragma unroll
            for (int r = 0; r < 8; r++)
                P[r] = *(const float4*)(pRow + r * SPS + j);
            #pragma unroll
            for (int q = 0; q < 4; q++) {
                const float* up = uc + (j + q) * 8;
                F4U2 bA, bB;
                bA.f = *(const float4*)(up);
                bB.f = *(const float4*)(up + 4);
                const float* Pq = (const float*)P;
                #pragma unroll
                for (int r = 0; r < 8; r++) {
                    const ull d = dup2(Pq[r * 4 + q]);
                    fma2(acc2[r][0], d, bA.u[0]);
                    fma2(acc2[r][1], d, bA.u[1]);
                    fma2(acc2[r][2], d, bB.u[0]);
                    fma2(acc2[r][3], d, bB.u[1]);
                }
            }
        }

        if (valid) {
            #pragma unroll
            for (int r = 0; r < 8; r++) {
                float4 uA, uB;
                uA.x = lo32(acc2[r][0]); uA.y = hi32(acc2[r][0]);
                uA.z = lo32(acc2[r][1]); uA.w = hi32(acc2[r][1]);
                uB.x = lo32(acc2[r][2]); uB.y = hi32(acc2[r][2]);
                uB.z = lo32(acc2[r][3]); uB.w = hi32(acc2[r][3]);
                const float4 hA = *(const float4*)(HrowC + r * 200 + d0);
                const float4 hB = *(const float4*)(HrowC + r * 200 + d0 + 4);
                float* gp = GrowC + (size_t)r * 800;
                *(float4*)(gp + d0)           = hA;
                *(float4*)(gp + d0 + 4)       = hB;
                *(float4*)(gp + 200 + d0)     = uA;
                *(float4*)(gp + 200 + d0 + 4) = uB;
                float4 mA, mB;
                mA.x = hA.x * uA.x; mA.y = hA.y * uA.y; mA.z = hA.z * uA.z; mA.w = hA.w * uA.w;
                mB.x = hB.x * uB.x; mB.y = hB.y * uB.y; mB.z = hB.z * uB.z; mB.w = hB.w * uB.w;
                *(float4*)(gp + 400 + d0)     = mA;
                *(float4*)(gp + 400 + d0 + 4) = mB;
            }
        }
    }
}

// ---- fused tail: cluster of 8 CTAs per n; softmax(Smax) + Hbar + H*Hbar ----
__global__ void __launch_bounds__(256, 1) __cluster_dims__(8, 1, 1)
tail_fused(const float* __restrict__ H, const float* __restrict__ c_mask,
           float* __restrict__ G)
{
    __shared__ float sa[128];
    __shared__ float s_mx[8], s_E[8], s_M[8];
    __shared__ float red[8], redE[8], redM[8];
    __shared__ float part[8][208];
    __shared__ float ppart[200];
    __shared__ float hbar[200];

    const int bx = blockIdx.x;
    const int n = bx >> 3;
    const int s = bx & 7;           // == cluster rank
    const int tid = threadIdx.x;
    const int wid = tid >> 5, lane = tid & 31;

    // local chunk v, c
    float v = -3.4e38f, c = 0.f;
    if (tid < 128) {
        c = c_mask[n * 1024 + s * 128 + tid];
        v = g_Smax[n * 1024 + s * 128 + tid] * c;
    }
    // block max
    float mx = v;
    #pragma unroll
    for (int o = 16; o > 0; o >>= 1) mx = fmaxf(mx, __shfl_xor_sync(0xffffffffu, mx, o));
    if (lane == 0) red[wid] = mx;
    __syncthreads();
    mx = red[0];
    #pragma unroll
    for (int i = 1; i < 8; i++) mx = fmaxf(mx, red[i]);

    // broadcast local max to all ranks' s_mx[s]
    if (tid == 0) {
        const unsigned a = smem_u32(&s_mx[s]);
        #pragma unroll
        for (int r = 0; r < 8; r++) st_cluster_f32(a, r, mx);
    }
    CLUSTER_SYNC_();

    float gmx = s_mx[0];
    #pragma unroll
    for (int i = 1; i < 8; i++) gmx = fmaxf(gmx, s_mx[i]);

    // local E, M ; stash unscaled e*c in sa
    float e = 0.f;
    if (tid < 128) {
        e = __expf(v - gmx);
        sa[tid] = e * c;
    }
    float El = e, Ml = e * c;
    #pragma unroll
    for (int o = 16; o > 0; o >>= 1) {
        El += __shfl_xor_sync(0xffffffffu, El, o);
        Ml += __shfl_xor_sync(0xffffffffu, Ml, o);
    }
    if (lane == 0) { redE[wid] = El; redM[wid] = Ml; }
    __syncthreads();
    El = 0.f; Ml = 0.f;
    #pragma unroll
    for (int i = 0; i < 8; i++) { El += redE[i]; Ml += redM[i]; }
    if (tid == 0) {
        const unsigned aE = smem_u32(&s_E[s]);
        const unsigned aM = smem_u32(&s_M[s]);
        #pragma unroll
        for (int r = 0; r < 8; r++) { st_cluster_f32(aE, r, El); st_cluster_f32(aM, r, Ml); }
    }
    CLUSTER_SYNC_();

    float Et = 0.f, Mt = 0.f;
    #pragma unroll
    for (int i = 0; i < 8; i++) { Et += s_E[i]; Mt += s_M[i]; }
    const float inv = 1.0f / (Mt + 1e-13f * Et);

    // partial Hbar over this chunk's 128 rows (unscaled weights sa)
    const int d0v = lane * 4;
    const int d1v = 128 + lane * 4;
    const bool v1 = (lane < 18);
    float4 a0 = {0.f, 0.f, 0.f, 0.f}, a1 = {0.f, 0.f, 0.f, 0.f};
    const float* hb = H + (size_t)n * 204800 + (size_t)s * 128 * 200;
    #pragma unroll 4
    for (int t = wid * 16; t < wid * 16 + 16; t++) {
        const float av = sa[t];
        const float* hr = hb + (size_t)t * 200;
        const float4 h0 = *(const float4*)(hr + d0v);
        a0.x += av * h0.x; a0.y += av * h0.y; a0.z += av * h0.z; a0.w += av * h0.w;
        if (v1) {
            const float4 h1 = *(const float4*)(hr + d1v);
            a1.x += av * h1.x; a1.y += av * h1.y; a1.z += av * h1.z; a1.w += av * h1.w;
        }
    }
    *(float4*)(&part[wid][d0v]) = a0;
    if (v1) *(float4*)(&part[wid][d1v]) = a1;
    __syncthreads();

    if (tid < 200) {
        float sum = 0.f;
        #pragma unroll
        for (int w = 0; w < 8; w++) sum += part[w][tid];
        ppart[tid] = sum;
    }
    CLUSTER_SYNC_();   // all ranks' ppart ready

    if (tid < 200) {
        const unsigned a = smem_u32(&ppart[tid]);
        float sum = 0.f;
        #pragma unroll
        for (int r = 0; r < 8; r++) sum += ld_cluster_f32(a, r);
        hbar[tid] = sum * inv;
    }
    CLUSTER_SYNC_();   // all ranks done reading peers' ppart
    __syncthreads();

    // product: G[n, chunk rows, 600:800] = H * hbar
    float* gb = G + (size_t)(n * 1024 + s * 128) * 800;
    #pragma unroll 1
    for (int i = tid; i < 6400; i += 256) {
        const int r = i / 50;
        const int cc = i - r * 50;
        const float4 h4 = *(const float4*)(hb + (size_t)r * 200 + cc * 4);
        const float4 b4 = *(const float4*)(hbar + cc * 4);
        float4 o;
        o.x = h4.x * b4.x; o.y = h4.y * b4.y; o.z = h4.z * b4.z; o.w = h4.w * b4.w;
        *(float4*)(gb + (size_t)r * 800 + 600 + cc * 4) = o;
    }
}

extern "C" void kernel_launch(void* const* d_in, const int* in_sizes, int n_in,
                              void* d_out, int out_size)
{
    const float* H      = (const float*)d_in[0];
    const float* U      = (const float*)d_in[1];
    const float* c_mask = (const float*)d_in[2];
    const float* q_mask = (const float*)d_in[3];
    const float* w      = (const float*)d_in[4];
    const float* b      = (const float*)d_in[5];
    float* G = (float*)d_out;

    cudaFuncSetAttribute(bi_attn_main, cudaFuncAttributeMaxDynamicSharedMemorySize, SMEM_BYTES);

    dim3 g1(8, 64);
    bi_attn_main<<<g1, 256, SMEM_BYTES>>>(H, U, q_mask, w, b, G);
    tail_fused<<<512, 256>>>(H, c_mask, G);
}

// round 10
// speedup vs baseline: 1.1918x; 1.1882x over previous
#include <cuda_runtime.h>
#include <cuda_bf16.h>
#include <cstdint>

// BiAttention (BiDAF): N=64, T=1024, J=64, D2=200.
// Main kernel: warp-level mma.sync bf16 split-precision (works on compute_103 base target).
#define NEGV (-10000000.0f)
__device__ float g_Smax[64 * 1024];

// smem word-layout: row stride 68 words (hi words 0..31, lo 32..63, pad 4). 68 % 32 == 4
// -> fragment loads (banks 4r + c) conflict-free.
#define WRS 68
#define WB_B  8704        /* B region word base  (byte 34816) */
#define WB_UT 13056       /* Ut region word base (byte 52224) */
#define OFF_W   106624
#define OFF_HWH 109024
#define OFF_UWU 109536
#define OFF_QM  109792
#define SMEM_BYTES 110080

__device__ __forceinline__ void mma16816(float* c, uint32_t a0, uint32_t a1, uint32_t a2, uint32_t a3,
                                         uint32_t b0, uint32_t b1) {
    asm volatile("mma.sync.aligned.m16n8k16.row.col.f32.bf16.bf16.f32 "
                 "{%0,%1,%2,%3},{%4,%5,%6,%7},{%8,%9},{%0,%1,%2,%3};"
                 : "+f"(c[0]), "+f"(c[1]), "+f"(c[2]), "+f"(c[3])
                 : "r"(a0), "r"(a1), "r"(a2), "r"(a3), "r"(b0), "r"(b1));
}
__device__ __forceinline__ void bf16split2(float a, float b, uint32_t& hi, uint32_t& lo) {
    __nv_bfloat162 h2 = __floats2bfloat162_rn(a, b);
    float ra = a - __bfloat162float(__low2bfloat16(h2));
    float rb = b - __bfloat162float(__high2bfloat16(h2));
    __nv_bfloat162 l2 = __floats2bfloat162_rn(ra, rb);
    hi = *(uint32_t*)&h2; lo = *(uint32_t*)&l2;
}
__device__ __forceinline__ unsigned smem_u32(const void* p) {
    unsigned a;
    asm("{ .reg .u64 t; cvta.to.shared.u64 t, %1; cvt.u32.u64 %0, t; }" : "=r"(a) : "l"(p));
    return a;
}

__global__ void __launch_bounds__(256, 2)
bi_attn_main(const float* __restrict__ H, const float* __restrict__ U,
             const float* __restrict__ q_mask, const float* __restrict__ wv,
             const float* __restrict__ bptr, float* __restrict__ G)
{
    extern __shared__ char smc[];
    uint32_t* sm32 = (uint32_t*)smc;
    float* sW   = (float*)(smc + OFF_W);
    float* sHwh = (float*)(smc + OFF_HWH);
    float* sUwu = (float*)(smc + OFF_UWU);
    float* sQm  = (float*)(smc + OFF_QM);

    const int tid = threadIdx.x, wid = tid >> 5, lane = tid & 31;
    const int n = blockIdx.y, m0 = blockIdx.x * 128;

    for (int i = tid; i < 600; i += 256) sW[i] = wv[i];
    if (tid < 64) sQm[tid] = q_mask[n * 64 + tid];
    __syncthreads();

    // staging roles
    const int ar = tid >> 1, ah = tid & 1;          // A: 2 threads/row
    const int bj = tid >> 2, bq = tid & 3;          // B: 4 threads/row
    const float* hrow = H + (size_t)(n * 1024 + m0 + ar) * 200;
    const float* urow = U + (size_t)(n * 64 + bj) * 200;
    float hwh_acc = 0.f, uwu_acc = 0.f;

    // fragment roles
    const int r = lane >> 2, cq = lane & 3;
    const int arow0 = (wid * 16 + r) * WRS;
    const int arow1 = arow0 + 8 * WRS;

    float acc1[8][4];
    #pragma unroll
    for (int t = 0; t < 8; t++)
        #pragma unroll
        for (int u = 0; u < 4; u++) acc1[t][u] = 0.f;

    // ================= GEMM1: S = (H o w_hu) @ U^T, 4 K-chunks of 64 =================
    #pragma unroll 1
    for (int c = 0; c < 4; c++) {
        const int kb = c * 64;
        // A chunk stage (split products), fold hwh row-dot
        #pragma unroll
        for (int kk = 0; kk < 32; kk += 4) {
            const int kg = kb + ah * 32 + kk;
            uint32_t p0h = 0, p0l = 0, p1h = 0, p1l = 0;
            if (kg < 200) {
                const float4 h4 = *(const float4*)(hrow + kg);
                const float4 wh = *(const float4*)(sW + kg);
                const float4 wu = *(const float4*)(sW + 400 + kg);
                hwh_acc += h4.x * wh.x + h4.y * wh.y + h4.z * wh.z + h4.w * wh.w;
                bf16split2(h4.x * wu.x, h4.y * wu.y, p0h, p0l);
                bf16split2(h4.z * wu.z, h4.w * wu.w, p1h, p1l);
            }
            const int w0 = ar * WRS + ah * 16 + (kk >> 1);
            sm32[w0] = p0h; sm32[w0 + 1] = p1h;
            sm32[w0 + 32] = p0l; sm32[w0 + 33] = p1l;
        }
        // B chunk stage (U rows, split), fold uwu row-dot
        #pragma unroll
        for (int kk = 0; kk < 16; kk += 4) {
            const int kg = kb + bq * 16 + kk;
            uint32_t p0h = 0, p0l = 0, p1h = 0, p1l = 0;
            if (kg < 200) {
                const float4 u4 = *(const float4*)(urow + kg);
                const float4 wu = *(const float4*)(sW + 200 + kg);
                uwu_acc += u4.x * wu.x + u4.y * wu.y + u4.z * wu.z + u4.w * wu.w;
                bf16split2(u4.x, u4.y, p0h, p0l);
                bf16split2(u4.z, u4.w, p1h, p1l);
            }
            const int w0 = WB_B + bj * WRS + bq * 8 + (kk >> 1);
            sm32[w0] = p0h; sm32[w0 + 1] = p1h;
            sm32[w0 + 32] = p0l; sm32[w0 + 33] = p1l;
        }
        // Ut quarter-stage: Ut[d][j] = U[j][d], j in [c*16, c*16+16)
        if (tid < 200) {
            const float* up = U + (size_t)n * 12800 + tid;
            #pragma unroll
            for (int j = c * 16; j < c * 16 + 16; j += 2) {
                uint32_t ph, pl;
                bf16split2(up[(size_t)j * 200], up[(size_t)(j + 1) * 200], ph, pl);
                const int w0 = WB_UT + tid * WRS + (j >> 1);
                sm32[w0] = ph; sm32[w0 + 32] = pl;
            }
        }
        __syncthreads();
        // mma: 4 ksteps of 16
        #pragma unroll
        for (int kst = 0; kst < 4; kst++) {
            const int ko = kst * 8 + cq;
            const uint32_t ah0 = sm32[arow0 + ko],      ah1 = sm32[arow1 + ko];
            const uint32_t ah2 = sm32[arow0 + ko + 4],  ah3 = sm32[arow1 + ko + 4];
            const uint32_t al0 = sm32[arow0 + ko + 32], al1 = sm32[arow1 + ko + 32];
            const uint32_t al2 = sm32[arow0 + ko + 36], al3 = sm32[arow1 + ko + 36];
            #pragma unroll
            for (int nt = 0; nt < 8; nt++) {
                const int bw = WB_B + (nt * 8 + r) * WRS + ko;
                const uint32_t b0h = sm32[bw],      b1h = sm32[bw + 4];
                const uint32_t b0l = sm32[bw + 32], b1l = sm32[bw + 36];
                mma16816(acc1[nt], ah0, ah1, ah2, ah3, b0h, b1h);
                mma16816(acc1[nt], ah0, ah1, ah2, ah3, b0l, b1l);
                mma16816(acc1[nt], al0, al1, al2, al3, b0h, b1h);
            }
        }
        __syncthreads();
    }

    // row-dot reductions
    {
        float hv = hwh_acc + __shfl_xor_sync(0xffffffffu, hwh_acc, 1);
        if (ah == 0) sHwh[ar] = hv;
        float uv = uwu_acc;
        uv += __shfl_xor_sync(0xffffffffu, uv, 1);
        uv += __shfl_xor_sync(0xffffffffu, uv, 2);
        if (bq == 0) sUwu[bj] = uv;
    }
    __syncthreads();

    // ================= softmax over j (per fragment row, 4-lane groups) =================
    const float bval = bptr[0];
    const int row0 = wid * 16 + r, row1 = row0 + 8;
    const float hwh0 = sHwh[row0], hwh1 = sHwh[row1];
    float mx0 = -3.4e38f, mx1 = -3.4e38f, smx0 = -3.4e38f, smx1 = -3.4e38f;
    #pragma unroll
    for (int nt = 0; nt < 8; nt++) {
        #pragma unroll
        for (int i = 0; i < 2; i++) {
            const int nn = nt * 8 + cq * 2 + i;
            const float q = sQm[nn], uw = sUwu[nn];
            const float s0 = acc1[nt][i] + hwh0 + uw + bval;
            const float s1 = acc1[nt][2 + i] + hwh1 + uw + bval;
            acc1[nt][i] = s0 * q; acc1[nt][2 + i] = s1 * q;
            mx0 = fmaxf(mx0, s0 * q); mx1 = fmaxf(mx1, s1 * q);
            smx0 = fmaxf(smx0, (q != 0.f) ? s0 : NEGV);
            smx1 = fmaxf(smx1, (q != 0.f) ? s1 : NEGV);
        }
    }
    #pragma unroll
    for (int o = 1; o <= 2; o <<= 1) {
        mx0 = fmaxf(mx0, __shfl_xor_sync(0xffffffffu, mx0, o));
        mx1 = fmaxf(mx1, __shfl_xor_sync(0xffffffffu, mx1, o));
        smx0 = fmaxf(smx0, __shfl_xor_sync(0xffffffffu, smx0, o));
        smx1 = fmaxf(smx1, __shfl_xor_sync(0xffffffffu, smx1, o));
    }
    float E0 = 0.f, M0 = 0.f, E1 = 0.f, M1 = 0.f;
    #pragma unroll
    for (int nt = 0; nt < 8; nt++) {
        #pragma unroll
        for (int i = 0; i < 2; i++) {
            const int nn = nt * 8 + cq * 2 + i;
            const float q = sQm[nn];
            const float e0 = __expf(acc1[nt][i] - mx0);
            const float e1 = __expf(acc1[nt][2 + i] - mx1);
            E0 += e0; E1 += e1;
            const float q0 = e0 * q, q1 = e1 * q;
            M0 += q0; M1 += q1;
            acc1[nt][i] = q0; acc1[nt][2 + i] = q1;
        }
    }
    #pragma unroll
    for (int o = 1; o <= 2; o <<= 1) {
        E0 += __shfl_xor_sync(0xffffffffu, E0, o);
        M0 += __shfl_xor_sync(0xffffffffu, M0, o);
        E1 += __shfl_xor_sync(0xffffffffu, E1, o);
        M1 += __shfl_xor_sync(0xffffffffu, M1, o);
    }
    const float inv0 = 1.0f / (M0 + 1e-13f * E0);
    const float inv1 = 1.0f / (M1 + 1e-13f * E1);
    if (cq == 0) {
        g_Smax[(n << 10) + m0 + row0] = smx0;
        g_Smax[(n << 10) + m0 + row1] = smx1;
    }

    // write P (split) over A region (all GEMM1 A-reads completed before last sync)
    #pragma unroll
    for (int nt = 0; nt < 8; nt++) {
        uint32_t ph, pl;
        bf16split2(acc1[nt][0] * inv0, acc1[nt][1] * inv0, ph, pl);
        const int w0 = row0 * WRS + nt * 4 + cq;
        sm32[w0] = ph; sm32[w0 + 32] = pl;
        bf16split2(acc1[nt][2] * inv1, acc1[nt][3] * inv1, ph, pl);
        const int w1 = row1 * WRS + nt * 4 + cq;
        sm32[w1] = ph; sm32[w1 + 32] = pl;
    }
    __syncthreads();

    // ================= GEMM2: U_ = P @ U (N=200 in 2 passes), fused epilogue =================
    const size_t grow0 = (size_t)(n * 1024 + m0 + row0) * 800;
    const size_t grow1 = (size_t)(n * 1024 + m0 + row1) * 800;
    const float* hg0 = H + (size_t)(n * 1024 + m0 + row0) * 200;
    const float* hg1 = H + (size_t)(n * 1024 + m0 + row1) * 200;

    #pragma unroll
    for (int pass = 0; pass < 2; pass++) {
        const int NT = pass ? 12 : 13;
        const int dbase = pass * 104;
        float acc2[13][4];
        #pragma unroll
        for (int t = 0; t < 13; t++)
            #pragma unroll
            for (int u = 0; u < 4; u++) acc2[t][u] = 0.f;

        #pragma unroll
        for (int kst = 0; kst < 4; kst++) {
            const int ko = kst * 8 + cq;
            const uint32_t ah0 = sm32[arow0 + ko],      ah1 = sm32[arow1 + ko];
            const uint32_t ah2 = sm32[arow0 + ko + 4],  ah3 = sm32[arow1 + ko + 4];
            const uint32_t al0 = sm32[arow0 + ko + 32], al1 = sm32[arow1 + ko + 32];
            const uint32_t al2 = sm32[arow0 + ko + 36], al3 = sm32[arow1 + ko + 36];
            #pragma unroll
            for (int nt = 0; nt < 13; nt++) {
                if (nt < NT) {
                    const int bw = WB_UT + (dbase + nt * 8 + r) * WRS + ko;
                    const uint32_t b0h = sm32[bw],      b1h = sm32[bw + 4];
                    const uint32_t b0l = sm32[bw + 32], b1l = sm32[bw + 36];
                    mma16816(acc2[nt], ah0, ah1, ah2, ah3, b0h, b1h);
                    mma16816(acc2[nt], ah0, ah1, ah2, ah3, b0l, b1l);
                    mma16816(acc2[nt], al0, al1, al2, al3, b0h, b1h);
                }
            }
        }
        // epilogue: G[:, d] = H ; G[:, 200+d] = U_ ; G[:, 400+d] = H*U_
        #pragma unroll
        for (int nt = 0; nt < 13; nt++) {
            if (nt < NT) {
                const int d = dbase + nt * 8 + cq * 2;
                const float2 h0 = *(const float2*)(hg0 + d);
                const float2 h1 = *(const float2*)(hg1 + d);
                float2 u0 = {acc2[nt][0], acc2[nt][1]};
                float2 u1 = {acc2[nt][2], acc2[nt][3]};
                float2 m0v = {h0.x * u0.x, h0.y * u0.y};
                float2 m1v = {h1.x * u1.x, h1.y * u1.y};
                *(float2*)(G + grow0 + d)       = h0;
                *(float2*)(G + grow0 + 200 + d) = u0;
                *(float2*)(G + grow0 + 400 + d) = m0v;
                *(float2*)(G + grow1 + d)       = h1;
                *(float2*)(G + grow1 + 200 + d) = u1;
                *(float2*)(G + grow1 + 400 + d) = m1v;
            }
        }
    }
}

// ---- fused tail (unchanged, passing): cluster of 8 CTAs per n ----
__device__ __forceinline__ void st_cl(unsigned la, int rk, float v) {
    asm volatile("{ .reg .b32 ra; mapa.shared::cluster.u32 ra, %0, %1; st.shared::cluster.f32 [ra], %2; }"
                 :: "r"(la), "r"(rk), "f"(v) : "memory");
}
__device__ __forceinline__ float ld_cl(unsigned la, int rk) {
    float v;
    asm volatile("{ .reg .b32 ra; mapa.shared::cluster.u32 ra, %1, %2; ld.shared::cluster.f32 %0, [ra]; }"
                 : "=f"(v) : "r"(la), "r"(rk) : "memory");
    return v;
}
#define CSYNC() do { asm volatile("barrier.cluster.arrive.aligned;" ::: "memory"); \
                     asm volatile("barrier.cluster.wait.aligned;" ::: "memory"); } while (0)

__global__ void __launch_bounds__(256, 1) __cluster_dims__(8, 1, 1)
tail_fused(const float* __restrict__ H, const float* __restrict__ c_mask,
           float* __restrict__ G)
{
    __shared__ float sa[128];
    __shared__ float s_mx[8], s_E[8], s_M[8];
    __shared__ float red[8], redE[8], redM[8];
    __shared__ float part[8][208];
    __shared__ float ppart[200];
    __shared__ float hbar[200];

    const int bx = blockIdx.x, n = bx >> 3, s = bx & 7;
    const int tid = threadIdx.x, wid = tid >> 5, lane = tid & 31;

    float v = -3.4e38f, c = 0.f;
    if (tid < 128) {
        c = c_mask[n * 1024 + s * 128 + tid];
        v = g_Smax[n * 1024 + s * 128 + tid] * c;
    }
    float mx = v;
    #pragma unroll
    for (int o = 16; o > 0; o >>= 1) mx = fmaxf(mx, __shfl_xor_sync(0xffffffffu, mx, o));
    if (lane == 0) red[wid] = mx;
    __syncthreads();
    mx = red[0];
    #pragma unroll
    for (int i = 1; i < 8; i++) mx = fmaxf(mx, red[i]);
    if (tid == 0) {
        const unsigned a = smem_u32(&s_mx[s]);
        #pragma unroll
        for (int r = 0; r < 8; r++) st_cl(a, r, mx);
    }
    CSYNC();
    float gmx = s_mx[0];
    #pragma unroll
    for (int i = 1; i < 8; i++) gmx = fmaxf(gmx, s_mx[i]);

    float e = 0.f;
    if (tid < 128) { e = __expf(v - gmx); sa[tid] = e * c; }
    float El = e, Ml = e * c;
    #pragma unroll
    for (int o = 16; o > 0; o >>= 1) {
        El += __shfl_xor_sync(0xffffffffu, El, o);
        Ml += __shfl_xor_sync(0xffffffffu, Ml, o);
    }
    if (lane == 0) { redE[wid] = El; redM[wid] = Ml; }
    __syncthreads();
    El = 0.f; Ml = 0.f;
    #pragma unroll
    for (int i = 0; i < 8; i++) { El += redE[i]; Ml += redM[i]; }
    if (tid == 0) {
        const unsigned aE = smem_u32(&s_E[s]);
        const unsigned aM = smem_u32(&s_M[s]);
        #pragma unroll
        for (int r = 0; r < 8; r++) { st_cl(aE, r, El); st_cl(aM, r, Ml); }
    }
    CSYNC();
    float Et = 0.f, Mt = 0.f;
    #pragma unroll
    for (int i = 0; i < 8; i++) { Et += s_E[i]; Mt += s_M[i]; }
    const float inv = 1.0f / (Mt + 1e-13f * Et);

    const int d0v = lane * 4, d1v = 128 + lane * 4;
    const bool v1 = (lane < 18);
    float4 a0 = {0,0,0,0}, a1 = {0,0,0,0};
    const float* hb = H + (size_t)n * 204800 + (size_t)s * 128 * 200;
    #pragma unroll 4
    for (int t = wid * 16; t < wid * 16 + 16; t++) {
        const float av = sa[t];
        const float* hr = hb + (size_t)t * 200;
        const float4 h0 = *(const float4*)(hr + d0v);
        a0.x += av * h0.x; a0.y += av * h0.y; a0.z += av * h0.z; a0.w += av * h0.w;
        if (v1) {
            const float4 h1 = *(const float4*)(hr + d1v);
            a1.x += av * h1.x; a1.y += av * h1.y; a1.z += av * h1.z; a1.w += av * h1.w;
        }
    }
    *(float4*)(&part[wid][d0v]) = a0;
    if (v1) *(float4*)(&part[wid][d1v]) = a1;
    __syncthreads();
    if (tid < 200) {
        float sum = 0.f;
        #pragma unroll
        for (int w = 0; w < 8; w++) sum += part[w][tid];
        ppart[tid] = sum;
    }
    CSYNC();
    if (tid < 200) {
        const unsigned a = smem_u32(&ppart[tid]);
        float sum = 0.f;
        #pragma unroll
        for (int r = 0; r < 8; r++) sum += ld_cl(a, r);
        hbar[tid] = sum * inv;
    }
    CSYNC();
    __syncthreads();

    float* gb = G + (size_t)(n * 1024 + s * 128) * 800;
    #pragma unroll 1
    for (int i = tid; i < 6400; i += 256) {
        const int r = i / 50, cc = i - r * 50;
        const float4 h4 = *(const float4*)(hb + (size_t)r * 200 + cc * 4);
        const float4 b4 = *(const float4*)(hbar + cc * 4);
        float4 o = {h4.x * b4.x, h4.y * b4.y, h4.z * b4.z, h4.w * b4.w};
        *(float4*)(gb + (size_t)r * 800 + 600 + cc * 4) = o;
    }
}

extern "C" void kernel_launch(void* const* d_in, const int* in_sizes, int n_in,
                              void* d_out, int out_size)
{
    const float* H      = (const float*)d_in[0];
    const float* U      = (const float*)d_in[1];
    const float* c_mask = (const float*)d_in[2];
    const float* q_mask = (const float*)d_in[3];
    const float* w      = (const float*)d_in[4];
    const float* b      = (const float*)d_in[5];
    float* G = (float*)d_out;

    cudaFuncSetAttribute(bi_attn_main, cudaFuncAttributeMaxDynamicSharedMemorySize, SMEM_BYTES);
    dim3 g1(8, 64);
    bi_attn_main<<<g1, 256, SMEM_BYTES>>>(H, U, q_mask, w, b, G);
    tail_fused<<<512, 256>>>(H, c_mask, G);
}

// round 11
// speedup vs baseline: 1.2280x; 1.0304x over previous
#include <cuda_runtime.h>
#include <cuda_bf16.h>
#include <cstdint>

// BiAttention (BiDAF): N=64, T=1024, J=64, D2=200.
// Main kernel: warp-level mma.sync bf16 split-precision (compute_103-safe).
#define NEGV (-10000000.0f)
__device__ float g_Smax[64 * 1024];

// smem word-layout: row stride 68 words (hi 0..31, lo 32..63, pad 4). 68 % 32 == 4
#define WRS 68
#define WB_B  8704
#define WB_UT 13056
#define OFF_W   106624
#define OFF_HWH 109024
#define OFF_UWU 109536
#define OFF_QM  109792
#define SMEM_BYTES 110080

__device__ __forceinline__ void mma16816(float* c, uint32_t a0, uint32_t a1, uint32_t a2, uint32_t a3,
                                         uint32_t b0, uint32_t b1) {
    asm volatile("mma.sync.aligned.m16n8k16.row.col.f32.bf16.bf16.f32 "
                 "{%0,%1,%2,%3},{%4,%5,%6,%7},{%8,%9},{%0,%1,%2,%3};"
                 : "+f"(c[0]), "+f"(c[1]), "+f"(c[2]), "+f"(c[3])
                 : "r"(a0), "r"(a1), "r"(a2), "r"(a3), "r"(b0), "r"(b1));
}
__device__ __forceinline__ void bf16split2(float a, float b, uint32_t& hi, uint32_t& lo) {
    __nv_bfloat162 h2 = __floats2bfloat162_rn(a, b);
    float ra = a - __bfloat162float(__low2bfloat16(h2));
    float rb = b - __bfloat162float(__high2bfloat16(h2));
    __nv_bfloat162 l2 = __floats2bfloat162_rn(ra, rb);
    hi = *(uint32_t*)&h2; lo = *(uint32_t*)&l2;
}
__device__ __forceinline__ unsigned smem_u32(const void* p) {
    unsigned a;
    asm("{ .reg .u64 t; cvta.to.shared.u64 t, %1; cvt.u32.u64 %0, t; }" : "=r"(a) : "l"(p));
    return a;
}

__global__ void __launch_bounds__(256, 2)
bi_attn_main(const float* __restrict__ H, const float* __restrict__ U,
             const float* __restrict__ q_mask, const float* __restrict__ wv,
             const float* __restrict__ bptr, float* __restrict__ G)
{
    extern __shared__ char smc[];
    uint32_t* sm32 = (uint32_t*)smc;
    float* sW   = (float*)(smc + OFF_W);
    float* sHwh = (float*)(smc + OFF_HWH);
    float* sUwu = (float*)(smc + OFF_UWU);
    float* sQm  = (float*)(smc + OFF_QM);

    const int tid = threadIdx.x, wid = tid >> 5, lane = tid & 31;
    const int n = blockIdx.y, m0 = blockIdx.x * 128;

    for (int i = tid; i < 600; i += 256) sW[i] = wv[i];
    if (tid < 64) sQm[tid] = q_mask[n * 64 + tid];
    __syncthreads();

    const int ar = tid >> 1, ah = tid & 1;
    const int bj = tid >> 2, bq = tid & 3;
    const float* hrow = H + (size_t)(n * 1024 + m0 + ar) * 200;
    const float* urow = U + (size_t)(n * 64 + bj) * 200;
    float hwh_acc = 0.f, uwu_acc = 0.f;

    const int r = lane >> 2, cq = lane & 3;
    const int arow0 = (wid * 16 + r) * WRS;
    const int arow1 = arow0 + 8 * WRS;

    float acc1[8][4];
    #pragma unroll
    for (int t = 0; t < 8; t++)
        #pragma unroll
        for (int u = 0; u < 4; u++) acc1[t][u] = 0.f;

    // ================= GEMM1: S = (H o w_hu) @ U^T, 4 K-chunks of 64 =================
    #pragma unroll 1
    for (int c = 0; c < 4; c++) {
        const int kb = c * 64;
        #pragma unroll
        for (int kk = 0; kk < 32; kk += 4) {
            const int kg = kb + ah * 32 + kk;
            uint32_t p0h = 0, p0l = 0, p1h = 0, p1l = 0;
            if (kg < 200) {
                const float4 h4 = *(const float4*)(hrow + kg);
                const float4 wh = *(const float4*)(sW + kg);
                const float4 wu = *(const float4*)(sW + 400 + kg);
                hwh_acc += h4.x * wh.x + h4.y * wh.y + h4.z * wh.z + h4.w * wh.w;
                bf16split2(h4.x * wu.x, h4.y * wu.y, p0h, p0l);
                bf16split2(h4.z * wu.z, h4.w * wu.w, p1h, p1l);
            }
            const int w0 = ar * WRS + ah * 16 + (kk >> 1);
            sm32[w0] = p0h; sm32[w0 + 1] = p1h;
            sm32[w0 + 32] = p0l; sm32[w0 + 33] = p1l;
        }
        #pragma unroll
        for (int kk = 0; kk < 16; kk += 4) {
            const int kg = kb + bq * 16 + kk;
            uint32_t p0h = 0, p0l = 0, p1h = 0, p1l = 0;
            if (kg < 200) {
                const float4 u4 = *(const float4*)(urow + kg);
                const float4 wu = *(const float4*)(sW + 200 + kg);
                uwu_acc += u4.x * wu.x + u4.y * wu.y + u4.z * wu.z + u4.w * wu.w;
                bf16split2(u4.x, u4.y, p0h, p0l);
                bf16split2(u4.z, u4.w, p1h, p1l);
            }
            const int w0 = WB_B + bj * WRS + bq * 8 + (kk >> 1);
            sm32[w0] = p0h; sm32[w0 + 1] = p1h;
            sm32[w0 + 32] = p0l; sm32[w0 + 33] = p1l;
        }
        if (tid < 200) {
            const float* up = U + (size_t)n * 12800 + tid;
            #pragma unroll
            for (int j = c * 16; j < c * 16 + 16; j += 2) {
                uint32_t ph, pl;
                bf16split2(up[(size_t)j * 200], up[(size_t)(j + 1) * 200], ph, pl);
                const int w0 = WB_UT + tid * WRS + (j >> 1);
                sm32[w0] = ph; sm32[w0 + 32] = pl;
            }
        }
        __syncthreads();
        #pragma unroll
        for (int kst = 0; kst < 4; kst++) {
            const int ko = kst * 8 + cq;
            const uint32_t ah0 = sm32[arow0 + ko],      ah1 = sm32[arow1 + ko];
            const uint32_t ah2 = sm32[arow0 + ko + 4],  ah3 = sm32[arow1 + ko + 4];
            const uint32_t al0 = sm32[arow0 + ko + 32], al1 = sm32[arow1 + ko + 32];
            const uint32_t al2 = sm32[arow0 + ko + 36], al3 = sm32[arow1 + ko + 36];
            #pragma unroll
            for (int nt = 0; nt < 8; nt++) {
                const int bw = WB_B + (nt * 8 + r) * WRS + ko;
                const uint32_t b0h = sm32[bw],      b1h = sm32[bw + 4];
                const uint32_t b0l = sm32[bw + 32], b1l = sm32[bw + 36];
                mma16816(acc1[nt], ah0, ah1, ah2, ah3, b0h, b1h);
                mma16816(acc1[nt], ah0, ah1, ah2, ah3, b0l, b1l);
                mma16816(acc1[nt], al0, al1, al2, al3, b0h, b1h);
            }
        }
        __syncthreads();
    }

    {
        float hv = hwh_acc + __shfl_xor_sync(0xffffffffu, hwh_acc, 1);
        if (ah == 0) sHwh[ar] = hv;
        float uv = uwu_acc;
        uv += __shfl_xor_sync(0xffffffffu, uv, 1);
        uv += __shfl_xor_sync(0xffffffffu, uv, 2);
        if (bq == 0) sUwu[bj] = uv;
    }
    __syncthreads();

    // ================= softmax over j =================
    const float bval = bptr[0];
    const int row0 = wid * 16 + r, row1 = row0 + 8;
    const float hwh0 = sHwh[row0], hwh1 = sHwh[row1];
    float mx0 = -3.4e38f, mx1 = -3.4e38f, smx0 = -3.4e38f, smx1 = -3.4e38f;
    #pragma unroll
    for (int nt = 0; nt < 8; nt++) {
        #pragma unroll
        for (int i = 0; i < 2; i++) {
            const int nn = nt * 8 + cq * 2 + i;
            const float q = sQm[nn], uw = sUwu[nn];
            const float s0 = acc1[nt][i] + hwh0 + uw + bval;
            const float s1 = acc1[nt][2 + i] + hwh1 + uw + bval;
            acc1[nt][i] = s0 * q; acc1[nt][2 + i] = s1 * q;
            mx0 = fmaxf(mx0, s0 * q); mx1 = fmaxf(mx1, s1 * q);
            smx0 = fmaxf(smx0, (q != 0.f) ? s0 : NEGV);
            smx1 = fmaxf(smx1, (q != 0.f) ? s1 : NEGV);
        }
    }
    #pragma unroll
    for (int o = 1; o <= 2; o <<= 1) {
        mx0 = fmaxf(mx0, __shfl_xor_sync(0xffffffffu, mx0, o));
        mx1 = fmaxf(mx1, __shfl_xor_sync(0xffffffffu, mx1, o));
        smx0 = fmaxf(smx0, __shfl_xor_sync(0xffffffffu, smx0, o));
        smx1 = fmaxf(smx1, __shfl_xor_sync(0xffffffffu, smx1, o));
    }
    float E0 = 0.f, M0 = 0.f, E1 = 0.f, M1 = 0.f;
    #pragma unroll
    for (int nt = 0; nt < 8; nt++) {
        #pragma unroll
        for (int i = 0; i < 2; i++) {
            const int nn = nt * 8 + cq * 2 + i;
            const float q = sQm[nn];
            const float e0 = __expf(acc1[nt][i] - mx0);
            const float e1 = __expf(acc1[nt][2 + i] - mx1);
            E0 += e0; E1 += e1;
            const float q0 = e0 * q, q1 = e1 * q;
            M0 += q0; M1 += q1;
            acc1[nt][i] = q0; acc1[nt][2 + i] = q1;
        }
    }
    #pragma unroll
    for (int o = 1; o <= 2; o <<= 1) {
        E0 += __shfl_xor_sync(0xffffffffu, E0, o);
        M0 += __shfl_xor_sync(0xffffffffu, M0, o);
        E1 += __shfl_xor_sync(0xffffffffu, E1, o);
        M1 += __shfl_xor_sync(0xffffffffu, M1, o);
    }
    const float inv0 = 1.0f / (M0 + 1e-13f * E0);
    const float inv1 = 1.0f / (M1 + 1e-13f * E1);
    if (cq == 0) {
        g_Smax[(n << 10) + m0 + row0] = smx0;
        g_Smax[(n << 10) + m0 + row1] = smx1;
    }

    // write P (split) over A region
    #pragma unroll
    for (int nt = 0; nt < 8; nt++) {
        uint32_t ph, pl;
        bf16split2(acc1[nt][0] * inv0, acc1[nt][1] * inv0, ph, pl);
        const int w0 = row0 * WRS + nt * 4 + cq;
        sm32[w0] = ph; sm32[w0 + 32] = pl;
        bf16split2(acc1[nt][2] * inv1, acc1[nt][3] * inv1, ph, pl);
        const int w1 = row1 * WRS + nt * 4 + cq;
        sm32[w1] = ph; sm32[w1 + 32] = pl;
    }
    __syncthreads();

    // ================= GEMM2: U_ = P @ U, 5 passes x 5 n-tiles (no spills) =================
    const size_t grow0 = (size_t)(n * 1024 + m0 + row0) * 800;
    const size_t grow1 = (size_t)(n * 1024 + m0 + row1) * 800;
    const float* hg0 = H + (size_t)(n * 1024 + m0 + row0) * 200;
    const float* hg1 = H + (size_t)(n * 1024 + m0 + row1) * 200;

    #pragma unroll 1
    for (int pass = 0; pass < 5; pass++) {
        const int dbase = pass * 40;
        float acc2[5][4];
        #pragma unroll
        for (int t = 0; t < 5; t++)
            #pragma unroll
            for (int u = 0; u < 4; u++) acc2[t][u] = 0.f;

        #pragma unroll
        for (int kst = 0; kst < 4; kst++) {
            const int ko = kst * 8 + cq;
            const uint32_t ah0 = sm32[arow0 + ko],      ah1 = sm32[arow1 + ko];
            const uint32_t ah2 = sm32[arow0 + ko + 4],  ah3 = sm32[arow1 + ko + 4];
            const uint32_t al0 = sm32[arow0 + ko + 32], al1 = sm32[arow1 + ko + 32];
            const uint32_t al2 = sm32[arow0 + ko + 36], al3 = sm32[arow1 + ko + 36];
            #pragma unroll
            for (int nt = 0; nt < 5; nt++) {
                const int bw = WB_UT + (dbase + nt * 8 + r) * WRS + ko;
                const uint32_t b0h = sm32[bw],      b1h = sm32[bw + 4];
                const uint32_t b0l = sm32[bw + 32], b1l = sm32[bw + 36];
                mma16816(acc2[nt], ah0, ah1, ah2, ah3, b0h, b1h);
                mma16816(acc2[nt], ah0, ah1, ah2, ah3, b0l, b1l);
                mma16816(acc2[nt], al0, al1, al2, al3, b0h, b1h);
            }
        }
        #pragma unroll
        for (int nt = 0; nt < 5; nt++) {
            const int d = dbase + nt * 8 + cq * 2;
            const float2 h0 = *(const float2*)(hg0 + d);
            const float2 h1 = *(const float2*)(hg1 + d);
            float2 u0 = {acc2[nt][0], acc2[nt][1]};
            float2 u1 = {acc2[nt][2], acc2[nt][3]};
            float2 m0v = {h0.x * u0.x, h0.y * u0.y};
            float2 m1v = {h1.x * u1.x, h1.y * u1.y};
            *(float2*)(G + grow0 + d)       = h0;
            *(float2*)(G + grow0 + 200 + d) = u0;
            *(float2*)(G + grow0 + 400 + d) = m0v;
            *(float2*)(G + grow1 + d)       = h1;
            *(float2*)(G + grow1 + 200 + d) = u1;
            *(float2*)(G + grow1 + 400 + d) = m1v;
        }
    }
}

// ---- fused tail (unchanged, passing): cluster of 8 CTAs per n ----
__device__ __forceinline__ void st_cl(unsigned la, int rk, float v) {
    asm volatile("{ .reg .b32 ra; mapa.shared::cluster.u32 ra, %0, %1; st.shared::cluster.f32 [ra], %2; }"
                 :: "r"(la), "r"(rk), "f"(v) : "memory");
}
__device__ __forceinline__ float ld_cl(unsigned la, int rk) {
    float v;
    asm volatile("{ .reg .b32 ra; mapa.shared::cluster.u32 ra, %1, %2; ld.shared::cluster.f32 %0, [ra]; }"
                 : "=f"(v) : "r"(la), "r"(rk) : "memory");
    return v;
}
#define CSYNC() do { asm volatile("barrier.cluster.arrive.aligned;" ::: "memory"); \
                     asm volatile("barrier.cluster.wait.aligned;" ::: "memory"); } while (0)

__global__ void __launch_bounds__(256, 1) __cluster_dims__(8, 1, 1)
tail_fused(const float* __restrict__ H, const float* __restrict__ c_mask,
           float* __restrict__ G)
{
    __shared__ float sa[128];
    __shared__ float s_mx[8], s_E[8], s_M[8];
    __shared__ float red[8], redE[8], redM[8];
    __shared__ float part[8][208];
    __shared__ float ppart[200];
    __shared__ float hbar[200];

    const int bx = blockIdx.x, n = bx >> 3, s = bx & 7;
    const int tid = threadIdx.x, wid = tid >> 5, lane = tid & 31;

    float v = -3.4e38f, c = 0.f;
    if (tid < 128) {
        c = c_mask[n * 1024 + s * 128 + tid];
        v = g_Smax[n * 1024 + s * 128 + tid] * c;
    }
    float mx = v;
    #pragma unroll
    for (int o = 16; o > 0; o >>= 1) mx = fmaxf(mx, __shfl_xor_sync(0xffffffffu, mx, o));
    if (lane == 0) red[wid] = mx;
    __syncthreads();
    mx = red[0];
    #pragma unroll
    for (int i = 1; i < 8; i++) mx = fmaxf(mx, red[i]);
    if (tid == 0) {
        const unsigned a = smem_u32(&s_mx[s]);
        #pragma unroll
        for (int r = 0; r < 8; r++) st_cl(a, r, mx);
    }
    CSYNC();
    float gmx = s_mx[0];
    #pragma unroll
    for (int i = 1; i < 8; i++) gmx = fmaxf(gmx, s_mx[i]);

    float e = 0.f;
    if (tid < 128) { e = __expf(v - gmx); sa[tid] = e * c; }
    float El = e, Ml = e * c;
    #pragma unroll
    for (int o = 16; o > 0; o >>= 1) {
        El += __shfl_xor_sync(0xffffffffu, El, o);
        Ml += __shfl_xor_sync(0xffffffffu, Ml, o);
    }
    if (lane == 0) { redE[wid] = El; redM[wid] = Ml; }
    __syncthreads();
    El = 0.f; Ml = 0.f;
    #pragma unroll
    for (int i = 0; i < 8; i++) { El += redE[i]; Ml += redM[i]; }
    if (tid == 0) {
        const unsigned aE = smem_u32(&s_E[s]);
        const unsigned aM = smem_u32(&s_M[s]);
        #pragma unroll
        for (int r = 0; r < 8; r++) { st_cl(aE, r, El); st_cl(aM, r, Ml); }
    }
    CSYNC();
    float Et = 0.f, Mt = 0.f;
    #pragma unroll
    for (int i = 0; i < 8; i++) { Et += s_E[i]; Mt += s_M[i]; }
    const float inv = 1.0f / (Mt + 1e-13f * Et);

    const int d0v = lane * 4, d1v = 128 + lane * 4;
    const bool v1 = (lane < 18);
    float4 a0 = {0,0,0,0}, a1 = {0,0,0,0};
    const float* hb = H + (size_t)n * 204800 + (size_t)s * 128 * 200;
    #pragma unroll 4
    for (int t = wid * 16; t < wid * 16 + 16; t++) {
        const float av = sa[t];
        const float* hr = hb + (size_t)t * 200;
        const float4 h0 = *(const float4*)(hr + d0v);
        a0.x += av * h0.x; a0.y += av * h0.y; a0.z += av * h0.z; a0.w += av * h0.w;
        if (v1) {
            const float4 h1 = *(const float4*)(hr + d1v);
            a1.x += av * h1.x; a1.y += av * h1.y; a1.z += av * h1.z; a1.w += av * h1.w;
        }
    }
    *(float4*)(&part[wid][d0v]) = a0;
    if (v1) *(float4*)(&part[wid][d1v]) = a1;
    __syncthreads();
    if (tid < 200) {
        float sum = 0.f;
        #pragma unroll
        for (int w = 0; w < 8; w++) sum += part[w][tid];
        ppart[tid] = sum;
    }
    CSYNC();
    if (tid < 200) {
        const unsigned a = smem_u32(&ppart[tid]);
        float sum = 0.f;
        #pragma unroll
        for (int r = 0; r < 8; r++) sum += ld_cl(a, r);
        hbar[tid] = sum * inv;
    }
    CSYNC();
    __syncthreads();

    float* gb = G + (size_t)(n * 1024 + s * 128) * 800;
    #pragma unroll 1
    for (int i = tid; i < 6400; i += 256) {
        const int r = i / 50, cc = i - r * 50;
        const float4 h4 = *(const float4*)(hb + (size_t)r * 200 + cc * 4);
        const float4 b4 = *(const float4*)(hbar + cc * 4);
        float4 o = {h4.x * b4.x, h4.y * b4.y, h4.z * b4.z, h4.w * b4.w};
        *(float4*)(gb + (size_t)r * 800 + 600 + cc * 4) = o;
    }
}

extern "C" void kernel_launch(void* const* d_in, const int* in_sizes, int n_in,
                              void* d_out, int out_size)
{
    const float* H      = (const float*)d_in[0];
    const float* U      = (const float*)d_in[1];
    const float* c_mask = (const float*)d_in[2];
    const float* q_mask = (const float*)d_in[3];
    const float* w      = (const float*)d_in[4];
    const float* b      = (const float*)d_in[5];
    float* G = (float*)d_out;

    cudaFuncSetAttribute(bi_attn_main, cudaFuncAttributeMaxDynamicSharedMemorySize, SMEM_BYTES);
    dim3 g1(8, 64);
    bi_attn_main<<<g1, 256, SMEM_BYTES>>>(H, U, q_mask, w, b, G);
    tail_fused<<<512, 256>>>(H, c_mask, G);
}

// round 12
// speedup vs baseline: 1.3810x; 1.1246x over previous
#include <cuda_runtime.h>
#include <cuda_fp16.h>
#include <cstdint>

// BiAttention (BiDAF): N=64, T=1024, J=64, D2=200.
// Main kernel: warp-level mma.sync fp16 single-chain (compute_103-safe).
#define NEGV (-10000000.0f)
__device__ float g_Smax[64 * 1024];

// smem word-layout: row stride 68 words (hi plane 0..31, pad). 68 % 32 == 4 -> conflict-free frags.
#define WRS 68
#define WB_B  8704
#define WB_UT 13056
#define OFF_W   106624
#define OFF_HWH 109024
#define OFF_UWU 109536
#define OFF_QM  109792
#define SMEM_BYTES 110080

__device__ __forceinline__ void mma16816(float* c, uint32_t a0, uint32_t a1, uint32_t a2, uint32_t a3,
                                         uint32_t b0, uint32_t b1) {
    asm volatile("mma.sync.aligned.m16n8k16.row.col.f32.f16.f16.f32 "
                 "{%0,%1,%2,%3},{%4,%5,%6,%7},{%8,%9},{%0,%1,%2,%3};"
                 : "+f"(c[0]), "+f"(c[1]), "+f"(c[2]), "+f"(c[3])
                 : "r"(a0), "r"(a1), "r"(a2), "r"(a3), "r"(b0), "r"(b1));
}
__device__ __forceinline__ uint32_t pack2h(float a, float b) {
    __half2 h = __floats2half2_rn(a, b);
    return *(uint32_t*)&h;
}
__device__ __forceinline__ unsigned smem_u32(const void* p) {
    unsigned a;
    asm("{ .reg .u64 t; cvta.to.shared.u64 t, %1; cvt.u32.u64 %0, t; }" : "=r"(a) : "l"(p));
    return a;
}

__global__ void __launch_bounds__(256, 2)
bi_attn_main(const float* __restrict__ H, const float* __restrict__ U,
             const float* __restrict__ q_mask, const float* __restrict__ wv,
             const float* __restrict__ bptr, float* __restrict__ G)
{
    extern __shared__ char smc[];
    uint32_t* sm32 = (uint32_t*)smc;
    float* sW   = (float*)(smc + OFF_W);
    float* sHwh = (float*)(smc + OFF_HWH);
    float* sUwu = (float*)(smc + OFF_UWU);
    float* sQm  = (float*)(smc + OFF_QM);

    const int tid = threadIdx.x, wid = tid >> 5, lane = tid & 31;
    const int n = blockIdx.y, m0 = blockIdx.x * 128;

    for (int i = tid; i < 600; i += 256) sW[i] = wv[i];
    if (tid < 64) sQm[tid] = q_mask[n * 64 + tid];
    __syncthreads();

    const int ar = tid >> 1, ah = tid & 1;
    const int bj = tid >> 2, bq = tid & 3;
    const float* hrow = H + (size_t)(n * 1024 + m0 + ar) * 200;
    const float* urow = U + (size_t)(n * 64 + bj) * 200;
    float hwh_acc = 0.f, uwu_acc = 0.f;

    const int r = lane >> 2, cq = lane & 3;
    const int arow0 = (wid * 16 + r) * WRS;
    const int arow1 = arow0 + 8 * WRS;

    float acc1[8][4];
    #pragma unroll
    for (int t = 0; t < 8; t++)
        #pragma unroll
        for (int u = 0; u < 4; u++) acc1[t][u] = 0.f;

    // ================= GEMM1: S = (H o w_hu) @ U^T, 4 K-chunks of 64 (trimmed) =================
    #pragma unroll 1
    for (int c = 0; c < 4; c++) {
        const int kb = c * 64;
        #pragma unroll
        for (int kk = 0; kk < 32; kk += 4) {
            const int kg = kb + ah * 32 + kk;
            uint32_t p0 = 0, p1 = 0;
            if (kg < 200) {
                const float4 h4 = *(const float4*)(hrow + kg);
                const float4 wh = *(const float4*)(sW + kg);
                const float4 wu = *(const float4*)(sW + 400 + kg);
                hwh_acc += h4.x * wh.x + h4.y * wh.y + h4.z * wh.z + h4.w * wh.w;
                p0 = pack2h(h4.x * wu.x, h4.y * wu.y);
                p1 = pack2h(h4.z * wu.z, h4.w * wu.w);
            }
            const int w0 = ar * WRS + ah * 16 + (kk >> 1);
            sm32[w0] = p0; sm32[w0 + 1] = p1;
        }
        #pragma unroll
        for (int kk = 0; kk < 16; kk += 4) {
            const int kg = kb + bq * 16 + kk;
            uint32_t p0 = 0, p1 = 0;
            if (kg < 200) {
                const float4 u4 = *(const float4*)(urow + kg);
                const float4 wu = *(const float4*)(sW + 200 + kg);
                uwu_acc += u4.x * wu.x + u4.y * wu.y + u4.z * wu.z + u4.w * wu.w;
                p0 = pack2h(u4.x, u4.y);
                p1 = pack2h(u4.z, u4.w);
            }
            const int w0 = WB_B + bj * WRS + bq * 8 + (kk >> 1);
            sm32[w0] = p0; sm32[w0 + 1] = p1;
        }
        if (tid < 200) {
            const float* up = U + (size_t)n * 12800 + tid;
            #pragma unroll
            for (int j = c * 16; j < c * 16 + 16; j += 2) {
                const int w0 = WB_UT + tid * WRS + (j >> 1);
                sm32[w0] = pack2h(up[(size_t)j * 200], up[(size_t)(j + 1) * 200]);
            }
        }
        __syncthreads();
        const int nks = (c < 3) ? 4 : 1;   // chunk 3: only k=192..207 real
        #pragma unroll
        for (int kst = 0; kst < 4; kst++) {
            if (kst < nks) {
                const int ko = kst * 8 + cq;
                const uint32_t a0 = sm32[arow0 + ko],     a1 = sm32[arow1 + ko];
                const uint32_t a2 = sm32[arow0 + ko + 4], a3 = sm32[arow1 + ko + 4];
                #pragma unroll
                for (int nt = 0; nt < 8; nt++) {
                    const int bw = WB_B + (nt * 8 + r) * WRS + ko;
                    mma16816(acc1[nt], a0, a1, a2, a3, sm32[bw], sm32[bw + 4]);
                }
            }
        }
        __syncthreads();
    }

    {
        float hv = hwh_acc + __shfl_xor_sync(0xffffffffu, hwh_acc, 1);
        if (ah == 0) sHwh[ar] = hv;
        float uv = uwu_acc;
        uv += __shfl_xor_sync(0xffffffffu, uv, 1);
        uv += __shfl_xor_sync(0xffffffffu, uv, 2);
        if (bq == 0) sUwu[bj] = uv;
    }
    __syncthreads();

    // ================= softmax over j =================
    const float bval = bptr[0];
    const int row0 = wid * 16 + r, row1 = row0 + 8;
    const float hwh0 = sHwh[row0], hwh1 = sHwh[row1];
    float mx0 = -3.4e38f, mx1 = -3.4e38f, smx0 = -3.4e38f, smx1 = -3.4e38f;
    #pragma unroll
    for (int nt = 0; nt < 8; nt++) {
        #pragma unroll
        for (int i = 0; i < 2; i++) {
            const int nn = nt * 8 + cq * 2 + i;
            const float q = sQm[nn], uw = sUwu[nn];
            const float s0 = acc1[nt][i] + hwh0 + uw + bval;
            const float s1 = acc1[nt][2 + i] + hwh1 + uw + bval;
            acc1[nt][i] = s0 * q; acc1[nt][2 + i] = s1 * q;
            mx0 = fmaxf(mx0, s0 * q); mx1 = fmaxf(mx1, s1 * q);
            smx0 = fmaxf(smx0, (q != 0.f) ? s0 : NEGV);
            smx1 = fmaxf(smx1, (q != 0.f) ? s1 : NEGV);
        }
    }
    #pragma unroll
    for (int o = 1; o <= 2; o <<= 1) {
        mx0 = fmaxf(mx0, __shfl_xor_sync(0xffffffffu, mx0, o));
        mx1 = fmaxf(mx1, __shfl_xor_sync(0xffffffffu, mx1, o));
        smx0 = fmaxf(smx0, __shfl_xor_sync(0xffffffffu, smx0, o));
        smx1 = fmaxf(smx1, __shfl_xor_sync(0xffffffffu, smx1, o));
    }
    float E0 = 0.f, M0 = 0.f, E1 = 0.f, M1 = 0.f;
    #pragma unroll
    for (int nt = 0; nt < 8; nt++) {
        #pragma unroll
        for (int i = 0; i < 2; i++) {
            const int nn = nt * 8 + cq * 2 + i;
            const float q = sQm[nn];
            const float e0 = __expf(acc1[nt][i] - mx0);
            const float e1 = __expf(acc1[nt][2 + i] - mx1);
            E0 += e0; E1 += e1;
            const float q0 = e0 * q, q1 = e1 * q;
            M0 += q0; M1 += q1;
            acc1[nt][i] = q0; acc1[nt][2 + i] = q1;
        }
    }
    #pragma unroll
    for (int o = 1; o <= 2; o <<= 1) {
        E0 += __shfl_xor_sync(0xffffffffu, E0, o);
        M0 += __shfl_xor_sync(0xffffffffu, M0, o);
        E1 += __shfl_xor_sync(0xffffffffu, E1, o);
        M1 += __shfl_xor_sync(0xffffffffu, M1, o);
    }
    const float inv0 = 1.0f / (M0 + 1e-13f * E0);
    const float inv1 = 1.0f / (M1 + 1e-13f * E1);
    if (cq == 0) {
        g_Smax[(n << 10) + m0 + row0] = smx0;
        g_Smax[(n << 10) + m0 + row1] = smx1;
    }

    // write P (fp16) over A region
    #pragma unroll
    for (int nt = 0; nt < 8; nt++) {
        sm32[row0 * WRS + nt * 4 + cq] = pack2h(acc1[nt][0] * inv0, acc1[nt][1] * inv0);
        sm32[row1 * WRS + nt * 4 + cq] = pack2h(acc1[nt][2] * inv1, acc1[nt][3] * inv1);
    }
    __syncthreads();

    // ================= GEMM2: U_ = P @ U, 5 passes x 5 n-tiles =================
    const size_t grow0 = (size_t)(n * 1024 + m0 + row0) * 800;
    const size_t grow1 = (size_t)(n * 1024 + m0 + row1) * 800;
    const float* hg0 = H + (size_t)(n * 1024 + m0 + row0) * 200;
    const float* hg1 = H + (size_t)(n * 1024 + m0 + row1) * 200;

    #pragma unroll 1
    for (int pass = 0; pass < 5; pass++) {
        const int dbase = pass * 40;
        float acc2[5][4];
        #pragma unroll
        for (int t = 0; t < 5; t++)
            #pragma unroll
            for (int u = 0; u < 4; u++) acc2[t][u] = 0.f;

        #pragma unroll
        for (int kst = 0; kst < 4; kst++) {
            const int ko = kst * 8 + cq;
            const uint32_t a0 = sm32[arow0 + ko],     a1 = sm32[arow1 + ko];
            const uint32_t a2 = sm32[arow0 + ko + 4], a3 = sm32[arow1 + ko + 4];
            #pragma unroll
            for (int nt = 0; nt < 5; nt++) {
                const int bw = WB_UT + (dbase + nt * 8 + r) * WRS + ko;
                mma16816(acc2[nt], a0, a1, a2, a3, sm32[bw], sm32[bw + 4]);
            }
        }
        #pragma unroll
        for (int nt = 0; nt < 5; nt++) {
            const int d = dbase + nt * 8 + cq * 2;
            const float2 h0 = *(const float2*)(hg0 + d);
            const float2 h1 = *(const float2*)(hg1 + d);
            float2 u0 = {acc2[nt][0], acc2[nt][1]};
            float2 u1 = {acc2[nt][2], acc2[nt][3]};
            float2 m0v = {h0.x * u0.x, h0.y * u0.y};
            float2 m1v = {h1.x * u1.x, h1.y * u1.y};
            *(float2*)(G + grow0 + d)       = h0;
            *(float2*)(G + grow0 + 200 + d) = u0;
            *(float2*)(G + grow0 + 400 + d) = m0v;
            *(float2*)(G + grow1 + d)       = h1;
            *(float2*)(G + grow1 + 200 + d) = u1;
            *(float2*)(G + grow1 + 400 + d) = m1v;
        }
    }
}

// ---- fused tail (unchanged, passing): cluster of 8 CTAs per n ----
__device__ __forceinline__ void st_cl(unsigned la, int rk, float v) {
    asm volatile("{ .reg .b32 ra; mapa.shared::cluster.u32 ra, %0, %1; st.shared::cluster.f32 [ra], %2; }"
                 :: "r"(la), "r"(rk), "f"(v) : "memory");
}
__device__ __forceinline__ float ld_cl(unsigned la, int rk) {
    float v;
    asm volatile("{ .reg .b32 ra; mapa.shared::cluster.u32 ra, %1, %2; ld.shared::cluster.f32 %0, [ra]; }"
                 : "=f"(v) : "r"(la), "r"(rk) : "memory");
    return v;
}
#define CSYNC() do { asm volatile("barrier.cluster.arrive.aligned;" ::: "memory"); \
                     asm volatile("barrier.cluster.wait.aligned;" ::: "memory"); } while (0)

__global__ void __launch_bounds__(256, 1) __cluster_dims__(8, 1, 1)
tail_fused(const float* __restrict__ H, const float* __restrict__ c_mask,
           float* __restrict__ G)
{
    __shared__ float sa[128];
    __shared__ float s_mx[8], s_E[8], s_M[8];
    __shared__ float red[8], redE[8], redM[8];
    __shared__ float part[8][208];
    __shared__ float ppart[200];
    __shared__ float hbar[200];

    const int bx = blockIdx.x, n = bx >> 3, s = bx & 7;
    const int tid = threadIdx.x, wid = tid >> 5, lane = tid & 31;

    float v = -3.4e38f, c = 0.f;
    if (tid < 128) {
        c = c_mask[n * 1024 + s * 128 + tid];
        v = g_Smax[n * 1024 + s * 128 + tid] * c;
    }
    float mx = v;
    #pragma unroll
    for (int o = 16; o > 0; o >>= 1) mx = fmaxf(mx, __shfl_xor_sync(0xffffffffu, mx, o));
    if (lane == 0) red[wid] = mx;
    __syncthreads();
    mx = red[0];
    #pragma unroll
    for (int i = 1; i < 8; i++) mx = fmaxf(mx, red[i]);
    if (tid == 0) {
        const unsigned a = smem_u32(&s_mx[s]);
        #pragma unroll
        for (int r = 0; r < 8; r++) st_cl(a, r, mx);
    }
    CSYNC();
    float gmx = s_mx[0];
    #pragma unroll
    for (int i = 1; i < 8; i++) gmx = fmaxf(gmx, s_mx[i]);

    float e = 0.f;
    if (tid < 128) { e = __expf(v - gmx); sa[tid] = e * c; }
    float El = e, Ml = e * c;
    #pragma unroll
    for (int o = 16; o > 0; o >>= 1) {
        El += __shfl_xor_sync(0xffffffffu, El, o);
        Ml += __shfl_xor_sync(0xffffffffu, Ml, o);
    }
    if (lane == 0) { redE[wid] = El; redM[wid] = Ml; }
    __syncthreads();
    El = 0.f; Ml = 0.f;
    #pragma unroll
    for (int i = 0; i < 8; i++) { El += redE[i]; Ml += redM[i]; }
    if (tid == 0) {
        const unsigned aE = smem_u32(&s_E[s]);
        const unsigned aM = smem_u32(&s_M[s]);
        #pragma unroll
        for (int r = 0; r < 8; r++) { st_cl(aE, r, El); st_cl(aM, r, Ml); }
    }
    CSYNC();
    float Et = 0.f, Mt = 0.f;
    #pragma unroll
    for (int i = 0; i < 8; i++) { Et += s_E[i]; Mt += s_M[i]; }
    const float inv = 1.0f / (Mt + 1e-13f * Et);

    const int d0v = lane * 4, d1v = 128 + lane * 4;
    const bool v1 = (lane < 18);
    float4 a0 = {0,0,0,0}, a1 = {0,0,0,0};
    const float* hb = H + (size_t)n * 204800 + (size_t)s * 128 * 200;
    #pragma unroll 4
    for (int t = wid * 16; t < wid * 16 + 16; t++) {
        const float av = sa[t];
        const float* hr = hb + (size_t)t * 200;
        const float4 h0 = *(const float4*)(hr + d0v);
        a0.x += av * h0.x; a0.y += av * h0.y; a0.z += av * h0.z; a0.w += av * h0.w;
        if (v1) {
            const float4 h1 = *(const float4*)(hr + d1v);
            a1.x += av * h1.x; a1.y += av * h1.y; a1.z += av * h1.z; a1.w += av * h1.w;
        }
    }
    *(float4*)(&part[wid][d0v]) = a0;
    if (v1) *(float4*)(&part[wid][d1v]) = a1;
    __syncthreads();
    if (tid < 200) {
        float sum = 0.f;
        #pragma unroll
        for (int w = 0; w < 8; w++) sum += part[w][tid];
        ppart[tid] = sum;
    }
    CSYNC();
    if (tid < 200) {
        const unsigned a = smem_u32(&ppart[tid]);
        float sum = 0.f;
        #pragma unroll
        for (int r = 0; r < 8; r++) sum += ld_cl(a, r);
        hbar[tid] = sum * inv;
    }
    CSYNC();
    __syncthreads();

    float* gb = G + (size_t)(n * 1024 + s * 128) * 800;
    #pragma unroll 1
    for (int i = tid; i < 6400; i += 256) {
        const int r = i / 50, cc = i - r * 50;
        const float4 h4 = *(const float4*)(hb + (size_t)r * 200 + cc * 4);
        const float4 b4 = *(const float4*)(hbar + cc * 4);
        float4 o = {h4.x * b4.x, h4.y * b4.y, h4.z * b4.z, h4.w * b4.w};
        *(float4*)(gb + (size_t)r * 800 + 600 + cc * 4) = o;
    }
}

extern "C" void kernel_launch(void* const* d_in, const int* in_sizes, int n_in,
                              void* d_out, int out_size)
{
    const float* H      = (const float*)d_in[0];
    const float* U      = (const float*)d_in[1];
    const float* c_mask = (const float*)d_in[2];
    const float* q_mask = (const float*)d_in[3];
    const float* w      = (const float*)d_in[4];
    const float* b      = (const float*)d_in[5];
    float* G = (float*)d_out;

    cudaFuncSetAttribute(bi_attn_main, cudaFuncAttributeMaxDynamicSharedMemorySize, SMEM_BYTES);
    dim3 g1(8, 64);
    bi_attn_main<<<g1, 256, SMEM_BYTES>>>(H, U, q_mask, w, b, G);
    tail_fused<<<512, 256>>>(H, c_mask, G);
}